// round 14
// baseline (speedup 1.0000x reference)
#include <cuda_runtime.h>
#include <cuda_bf16.h>
#include <math.h>
#include <stdint.h>

#define E_EDGES 400000
#define NGROUPS 25000

// ===========================================================================
// PTX helpers (sm_80-class only — toolchain targets plain sm_103, no tcgen05)
// ===========================================================================
__device__ __forceinline__ uint32_t smem_u32(const void* p) {
    uint32_t a;
    asm("{ .reg .u64 t; cvta.to.shared.u64 t, %1; cvt.u32.u64 %0, t; }"
        : "=r"(a) : "l"(p));
    return a;
}

#define CP_ASYNC16(sm, gm) \
    asm volatile("cp.async.cg.shared.global [%0], [%1], 16;" \
        :: "r"(sm), "l"(gm) : "memory")
#define CP_COMMIT() asm volatile("cp.async.commit_group;" ::: "memory")
#define CP_WAIT(n)  asm volatile("cp.async.wait_group %0;" :: "n"(n) : "memory")

__device__ __forceinline__ void ldsm_x4(uint32_t* d, uint32_t addr) {
    asm volatile("ldmatrix.sync.aligned.m8n8.x4.shared.b16 {%0,%1,%2,%3}, [%4];"
        : "=r"(d[0]), "=r"(d[1]), "=r"(d[2]), "=r"(d[3]) : "r"(addr));
}

#define MMA16816(d, a, b) \
    asm volatile("mma.sync.aligned.m16n8k16.row.col.f32.bf16.bf16.f32 " \
        "{%0,%1,%2,%3}, {%4,%5,%6,%7}, {%8,%9}, {%0,%1,%2,%3};" \
        : "+f"((d)[0]), "+f"((d)[1]), "+f"((d)[2]), "+f"((d)[3]) \
        : "r"((a)[0]), "r"((a)[1]), "r"((a)[2]), "r"((a)[3]), \
          "r"((b)[0]), "r"((b)[1]))

// SW64 swizzle for 64-byte rows (BK=32 bf16)
__device__ __forceinline__ uint32_t sw(uint32_t off) {
    return off ^ ((off >> 3) & 0x30);
}

// ===========================================================================
// Scratch globals (no cudaMalloc allowed)
// ===========================================================================
__device__ __nv_bfloat16 g_hiB[(size_t)E_EDGES * 256];
__device__ __nv_bfloat16 g_loB[(size_t)E_EDGES * 256];
// fused layer-3 partial outputs (per y-tile, summed in edge_finalize)
__device__ float g_q0  [(size_t)E_EDGES * 32];
__device__ float g_q1  [(size_t)E_EDGES * 32];
__device__ float g_xnk0[(size_t)E_EDGES * 96];
__device__ float g_xnk1[(size_t)E_EDGES * 96];

__device__ float g_W2q [256 * 32];   // W2 @ Wqk  (fp32, [k][n])
__device__ float g_Wcat[256 * 96];   // [W2 | W2@Wk] (fp32, [k][n])
// Transposed + split weights, [n][k] layout (K contiguous)
__device__ __nv_bfloat16 g_W0t_hi[256 * 256], g_W0t_lo[256 * 256];
__device__ __nv_bfloat16 g_W1t_hi[256 * 256], g_W1t_lo[256 * 256];
__device__ __nv_bfloat16 g_W2qt_hi[32 * 256], g_W2qt_lo[32 * 256];
__device__ __nv_bfloat16 g_Wct_hi[96 * 256],  g_Wct_lo[96 * 256];

__device__ __forceinline__ void split2(float v, __nv_bfloat16& h, __nv_bfloat16& l) {
    h = __float2bfloat16_rn(v);
    l = __float2bfloat16_rn(v - __bfloat162float(h));
}

// ===========================================================================
// prep1: fold head projections: g_W2q = W2@Wqk, g_Wcat = [W2 | W2@Wk]
// ===========================================================================
__global__ void prep_fold(const float* __restrict__ W2,
                          const float* __restrict__ Wqk,
                          const float* __restrict__ Wk) {
    __shared__ float sQ[64 * 32];
    __shared__ float sK[64 * 32];
    int tid = threadIdx.x;
    for (int i = tid; i < 64 * 32; i += 256) { sQ[i] = Wqk[i]; sK[i] = Wk[i]; }
    __syncthreads();
    int r = tid;
    float w2r[64];
#pragma unroll
    for (int j = 0; j < 64; ++j) w2r[j] = W2[r * 64 + j];
#pragma unroll 4
    for (int c = 0; c < 32; ++c) {
        float aq = 0.f, ak = 0.f;
#pragma unroll
        for (int j = 0; j < 64; ++j) {
            aq = fmaf(w2r[j], sQ[j * 32 + c], aq);
            ak = fmaf(w2r[j], sK[j * 32 + c], ak);
        }
        g_W2q[r * 32 + c]       = aq;
        g_Wcat[r * 96 + 64 + c] = ak;
    }
#pragma unroll
    for (int j = 0; j < 64; ++j) g_Wcat[r * 96 + j] = w2r[j];
}

// ===========================================================================
// prep2: transpose to [n][k] and split all GEMM weights to bf16 hi/lo
// ===========================================================================
__global__ void prep_transpose_split(const float* __restrict__ W0,
                                     const float* __restrict__ W1) {
    int t = blockIdx.x * 256 + threadIdx.x;
    int o = t >> 8, i = t & 255;
    __nv_bfloat16 h, l;
    split2(W0[i * 256 + o], h, l);  g_W0t_hi[t] = h;  g_W0t_lo[t] = l;
    split2(W1[i * 256 + o], h, l);  g_W1t_hi[t] = h;  g_W1t_lo[t] = l;
    if (o < 32) { split2(g_W2q[i * 32 + o], h, l);  g_W2qt_hi[t] = h; g_W2qt_lo[t] = l; }
    if (o < 96) { split2(g_Wcat[i * 96 + o], h, l); g_Wct_hi[t] = h;  g_Wct_lo[t] = l; }
}

// ===========================================================================
// HMMA GEMM, bf16x3: C = Ah*Bh + Al*Bh + Ah*Bl.
// BM=128, BN=128, BK=32, 8 K-chunks. NSTAGE smem stages:
//   NSTAGE=3: one barrier/chunk, loads 2 ahead (L1 kernels).
//   NSTAGE=2: classic double buffer, two barriers/chunk (fused kernels; smem
//             budget is taken by the preloaded W3 region).
// 256 threads = 8 warps (4M x 2N); warp = 32 rows x 64 cols (NB=8 n8-tiles).
//
// FP32A:      A fp32 in gmem; LDG prefetch + in-register split + STS.
// SPLIT_RELU: epilogue = relu + re-split hi/lo bf16, width 256 (feeds L2).
// N3 > 0:     FUSED LAYER-3. W3 slice ([N3 x 128] x 2 splits, 4 K-chunks) is
//             prefetched by cp.async in the PROLOGUE (first commit group) into
//             a dedicated smem region and sits there through the mainloop.
//             Epilogue: relu+split full H2 tile into smem (overlaying the
//             stage buffers), ONE barrier, then 8 uninterrupted ldsm+MMA
//             iterations. fp32 partial [128,N3] -> out0 (y=0) / out1 (y=1).
// ===========================================================================
template <bool SPLIT_RELU, int N3, bool FP32A, int NSTAGE>
__global__ void __launch_bounds__(256, 2)
hmma_gemm(const void* __restrict__ Ah_, const __nv_bfloat16* __restrict__ Al,
          const __nv_bfloat16* __restrict__ Bh, const __nv_bfloat16* __restrict__ Bl,
          const __nv_bfloat16* __restrict__ W3h, const __nv_bfloat16* __restrict__ W3l,
          void* __restrict__ out0, void* __restrict__ out1) {
    constexpr int BN    = 128;
    constexpr int NB    = 8;                 // n8-tiles per warp = 64 cols
    constexpr int A_CH  = 128 * 64;          // bytes per A split per chunk
    constexpr int B_CH  = BN * 64;
    constexpr int STAGE = 2 * A_CH + 2 * B_CH;   // 32 KB

    extern __shared__ char smem[];
    const uint32_t s0 = smem_u32(smem);
    const uint32_t w3off = s0 + NSTAGE * STAGE;  // W3 region (N3>0 only)

    const int tid  = threadIdx.x;
    const int lane = tid & 31;
    const int wid  = tid >> 5;
    const int m0w  = (wid & 3) * 32;
    const int n0w  = (wid >> 2) * 64;
    const int row0 = blockIdx.x * 128;
    const int col0 = blockIdx.y * BN;

    const float* Afp = (const float*)Ah_;
    const __nv_bfloat16* Ah = (const __nv_bfloat16*)Ah_;

    float acc[2][NB][4];
#pragma unroll
    for (int mi = 0; mi < 2; ++mi)
#pragma unroll
        for (int ni = 0; ni < NB; ++ni)
#pragma unroll
            for (int v = 0; v < 4; ++v) acc[mi][ni][v] = 0.f;

    float4 pf[4];  // FP32A prefetch

    auto loadB = [&](int c, int buf) {
        const int kk = c << 5;
#pragma unroll
        for (int i = tid; i < 2 * BN * 4; i += 256) {
            int sp = i / (BN * 4), idx = i % (BN * 4), n = idx >> 2, g = idx & 3;
            const __nv_bfloat16* src =
                (sp ? Bl : Bh) + (size_t)(col0 + n) * 256 + kk + g * 8;
            CP_ASYNC16(s0 + buf * STAGE + 2 * A_CH + sp * B_CH + sw(n * 64 + g * 16), src);
        }
    };
    auto loadA_cp = [&](int c, int buf) {
        const int kk = c << 5;
#pragma unroll
        for (int i = tid; i < 1024; i += 256) {
            int sp = i >> 9, idx = i & 511, r = idx >> 2, g = idx & 3;
            const __nv_bfloat16* src =
                (sp ? Al : Ah) + (size_t)(row0 + r) * 256 + kk + g * 8;
            CP_ASYNC16(s0 + buf * STAGE + sp * A_CH + sw(r * 64 + g * 16), src);
        }
    };
    auto ldA_f32 = [&](int c) {
        const int kk = c << 5;
#pragma unroll
        for (int j = 0; j < 4; ++j) {
            int f4 = tid + 256 * j;
            int r = f4 >> 3, c4 = f4 & 7;
            pf[j] = *(const float4*)(Afp + (size_t)(row0 + r) * 256 + kk + c4 * 4);
        }
    };
    auto stA_f32 = [&](int buf) {
#pragma unroll
        for (int j = 0; j < 4; ++j) {
            int f4 = tid + 256 * j;
            int r = f4 >> 3, c4 = f4 & 7;
            __nv_bfloat16 h0, l0, h1, l1, h2, l2, h3, l3;
            split2(pf[j].x, h0, l0); split2(pf[j].y, h1, l1);
            split2(pf[j].z, h2, l2); split2(pf[j].w, h3, l3);
            uint2 hw = make_uint2(
                (uint32_t)__bfloat16_as_ushort(h0) | ((uint32_t)__bfloat16_as_ushort(h1) << 16),
                (uint32_t)__bfloat16_as_ushort(h2) | ((uint32_t)__bfloat16_as_ushort(h3) << 16));
            uint2 lw = make_uint2(
                (uint32_t)__bfloat16_as_ushort(l0) | ((uint32_t)__bfloat16_as_ushort(l1) << 16),
                (uint32_t)__bfloat16_as_ushort(l2) | ((uint32_t)__bfloat16_as_ushort(l3) << 16));
            uint32_t off = buf * STAGE + sw(r * 64 + c4 * 8);
            *(uint2*)(smem + off)        = hw;
            *(uint2*)(smem + off + A_CH) = lw;
        }
    };

    auto computeChunk = [&](uint32_t st) {
        const uint32_t da = st;
        const uint32_t db = st + 2 * A_CH;
#pragma unroll
        for (int ks = 0; ks < 2; ++ks) {
            uint32_t ah[2][4], al[2][4];
#pragma unroll
            for (int mi = 0; mi < 2; ++mi) {
                uint32_t aoff = sw((m0w + mi * 16 + (lane & 15)) * 64 +
                                   ks * 32 + (lane >> 4) * 16);
                ldsm_x4(ah[mi], da + aoff);
                ldsm_x4(al[mi], da + A_CH + aoff);
            }
            uint32_t bh[NB][2], bl[NB][2];
#pragma unroll
            for (int np = 0; np < NB / 2; ++np) {
                uint32_t boff = sw((n0w + np * 16 + (lane >> 4) * 8 + (lane & 7)) * 64 +
                                   ks * 32 + ((lane >> 3) & 1) * 16);
                ldsm_x4(&bh[2 * np][0], db + boff);
                ldsm_x4(&bl[2 * np][0], db + B_CH + boff);
            }
#pragma unroll
            for (int mi = 0; mi < 2; ++mi)
#pragma unroll
                for (int ni = 0; ni < NB; ++ni)
                    MMA16816(acc[mi][ni], ah[mi], bh[ni]);
#pragma unroll
            for (int mi = 0; mi < 2; ++mi)
#pragma unroll
                for (int ni = 0; ni < NB; ++ni)
                    MMA16816(acc[mi][ni], al[mi], bh[ni]);
#pragma unroll
            for (int mi = 0; mi < 2; ++mi)
#pragma unroll
                for (int ni = 0; ni < NB; ++ni)
                    MMA16816(acc[mi][ni], ah[mi], bl[ni]);
        }
    };

    // ---- prologue ----
    if constexpr (N3 > 0) {
        // W3 prefetch: first commit group. Region layout: (sp*4+kc)*(N3*64),
        // rows of 64B, SW64-swizzled. kc = K-chunk within the CTA's 128 cols.
#pragma unroll
        for (int i = tid; i < 2 * 4 * N3 * 4; i += 256) {
            int sp = i / (4 * N3 * 4), r1 = i % (4 * N3 * 4);
            int kc = r1 / (N3 * 4),   r2 = r1 % (N3 * 4);
            int n  = r2 >> 2,         g  = r2 & 3;
            const __nv_bfloat16* src =
                (sp ? W3l : W3h) + (size_t)n * 256 + col0 + kc * 32 + g * 8;
            CP_ASYNC16(w3off + (sp * 4 + kc) * (N3 * 64) + sw(n * 64 + g * 16), src);
        }
        CP_COMMIT();
    }

    if constexpr (NSTAGE == 3) {
        if (FP32A) {
            ldA_f32(0); stA_f32(0);
            ldA_f32(1); stA_f32(1);
            loadB(0, 0); CP_COMMIT();
            loadB(1, 1); CP_COMMIT();
        } else {
            loadA_cp(0, 0); loadB(0, 0); CP_COMMIT();
            loadA_cp(1, 1); loadB(1, 1); CP_COMMIT();
        }
#pragma unroll 1
        for (int c = 0; c < 8; ++c) {
            if (c < 7) CP_WAIT(1); else CP_WAIT(0);
            __syncthreads();
            if (c < 6) {
                const int buf2 = (c + 2) % 3;
                if (FP32A) {
                    ldA_f32(c + 2);
                    loadB(c + 2, buf2);
                } else {
                    loadA_cp(c + 2, buf2);
                    loadB(c + 2, buf2);
                }
                CP_COMMIT();
            }
            computeChunk(s0 + (c % 3) * STAGE);
            if (FP32A && c < 6) stA_f32((c + 2) % 3);
        }
    } else {  // NSTAGE == 2 (fused kernels; FP32A unused here)
        loadA_cp(0, 0); loadB(0, 0); CP_COMMIT();
#pragma unroll 1
        for (int c = 0; c < 8; ++c) {
            if (c < 7) {
                loadA_cp(c + 1, (c + 1) & 1);
                loadB(c + 1, (c + 1) & 1);
                CP_COMMIT();
                CP_WAIT(1);
            } else {
                CP_WAIT(0);
            }
            __syncthreads();
            computeChunk(s0 + (c & 1) * STAGE);
            __syncthreads();
        }
    }

    // =======================================================================
    // Epilogues (compile-time selected)
    // =======================================================================
    if constexpr (SPLIT_RELU) {
        const int rbase = row0 + m0w + (lane >> 2);
        __nv_bfloat16* hi = (__nv_bfloat16*)out0;
        __nv_bfloat16* lo = (__nv_bfloat16*)out1;
#pragma unroll
        for (int mi = 0; mi < 2; ++mi) {
            const int r0 = rbase + mi * 16;
#pragma unroll
            for (int ni = 0; ni < NB; ++ni) {
                const int c = col0 + n0w + ni * 8 + (lane & 3) * 2;
#pragma unroll
                for (int h = 0; h < 2; ++h) {
                    float v0 = fmaxf(acc[mi][ni][2 * h],     0.f);
                    float v1 = fmaxf(acc[mi][ni][2 * h + 1], 0.f);
                    __nv_bfloat16 h0, l0, h1, l1;
                    split2(v0, h0, l0);
                    split2(v1, h1, l1);
                    size_t off = (size_t)(r0 + h * 8) * 256 + c;
                    *(uint32_t*)(hi + off) = (uint32_t)__bfloat16_as_ushort(h0) |
                                             ((uint32_t)__bfloat16_as_ushort(h1) << 16);
                    *(uint32_t*)(lo + off) = (uint32_t)__bfloat16_as_ushort(l0) |
                                             ((uint32_t)__bfloat16_as_ushort(l1) << 16);
                }
            }
        }
    }

    if constexpr (N3 > 0) {
        // ---- fused layer-3: G = relu(H2_tile) @ W3t[:, col0:col0+128]^T ----
        constexpr int NT3   = N3 / 8;        // n8-tiles per warp (warp spans all N3)
        constexpr int PH_SZ = 128 * 64;      // one K=32 chunk of P per split (8 KB)
        const uint32_t pH = s0;              // 4 chunks: 32 KB (overlays stages)
        const uint32_t pL = s0 + 4 * PH_SZ;  // 4 chunks: 32 KB

        __syncthreads();   // all mainloop smem reads finished; stage smem free

        // stage FULL P tile (this warp's 64 cols, rows it owns)
#pragma unroll
        for (int mi = 0; mi < 2; ++mi)
#pragma unroll
            for (int ni = 0; ni < NB; ++ni) {
                const int cl = n0w + ni * 8 + (lane & 3) * 2;  // col within 128
                const int j  = cl >> 5;
                const int cc = cl & 31;
#pragma unroll
                for (int rr = 0; rr < 2; ++rr) {
                    const int r = m0w + mi * 16 + (lane >> 2) + rr * 8;
                    float v0 = fmaxf(acc[mi][ni][2 * rr],     0.f);
                    float v1 = fmaxf(acc[mi][ni][2 * rr + 1], 0.f);
                    __nv_bfloat16 h0, l0, h1, l1;
                    split2(v0, h0, l0);
                    split2(v1, h1, l1);
                    uint32_t off = j * PH_SZ + sw(r * 64 + cc * 2);
                    *(uint32_t*)(smem + off) =
                        (uint32_t)__bfloat16_as_ushort(h0) |
                        ((uint32_t)__bfloat16_as_ushort(h1) << 16);
                    *(uint32_t*)(smem + 4 * PH_SZ + off) =
                        (uint32_t)__bfloat16_as_ushort(l0) |
                        ((uint32_t)__bfloat16_as_ushort(l1) << 16);
                }
            }

        float acc2[NT3][4];
#pragma unroll
        for (int ni = 0; ni < NT3; ++ni)
#pragma unroll
            for (int v = 0; v < 4; ++v) acc2[ni][v] = 0.f;

        __syncthreads();   // P visible; W3 already resident since prologue

#pragma unroll
        for (int jg = 0; jg < 4; ++jg) {
#pragma unroll
            for (int ks2 = 0; ks2 < 2; ++ks2) {
                uint32_t ph4[4], pl4[4];
                uint32_t aoff = jg * PH_SZ +
                                sw((wid * 16 + (lane & 15)) * 64 +
                                   ks2 * 32 + (lane >> 4) * 16);
                ldsm_x4(ph4, pH + aoff);
                ldsm_x4(pl4, pL + aoff);
                uint32_t w3h[NT3][2], w3l[NT3][2];
#pragma unroll
                for (int np2 = 0; np2 < NT3 / 2; ++np2) {
                    uint32_t rowoff = sw((np2 * 16 + (lane >> 4) * 8 + (lane & 7)) * 64 +
                                         ks2 * 32 + ((lane >> 3) & 1) * 16);
                    ldsm_x4(&w3h[2 * np2][0], w3off + jg * (N3 * 64) + rowoff);
                    ldsm_x4(&w3l[2 * np2][0], w3off + (4 + jg) * (N3 * 64) + rowoff);
                }
#pragma unroll
                for (int ni = 0; ni < NT3; ++ni) MMA16816(acc2[ni], ph4, w3h[ni]);
#pragma unroll
                for (int ni = 0; ni < NT3; ++ni) MMA16816(acc2[ni], pl4, w3h[ni]);
#pragma unroll
                for (int ni = 0; ni < NT3; ++ni) MMA16816(acc2[ni], ph4, w3l[ni]);
            }
        }

        // store fp32 partial [128, N3] to the per-y buffer
        float* op = (float*)(blockIdx.y ? out1 : out0);
        const int r0 = row0 + wid * 16 + (lane >> 2);
#pragma unroll
        for (int ni = 0; ni < NT3; ++ni) {
            const int c = ni * 8 + (lane & 3) * 2;
            *(float2*)(op + (size_t)r0 * N3 + c) =
                make_float2(acc2[ni][0], acc2[ni][1]);
            *(float2*)(op + (size_t)(r0 + 8) * N3 + c) =
                make_float2(acc2[ni][2], acc2[ni][3]);
        }
    }
}

// ===========================================================================
// Edge finalize with sorted-run compression. Block = 8 warps = 8 consecutive
// edges. Warp computes its weighted 64-vector + group id into smem; then 64
// threads sweep the 8 edges column-wise, merging same-group runs (ppr_idx is
// sorted, avg run length 16) and emitting ONE atomicAdd per run boundary.
// ===========================================================================
__global__ void edge_finalize(const float* __restrict__ ppr_scores,
                              const int* __restrict__ ppr_idx,
                              float* __restrict__ out) {
    __shared__ float sv[8 * 64];
    __shared__ int   sg[8];
    const int tid  = threadIdx.x;
    const int w    = tid >> 5;
    const int lane = tid & 31;
    const int edge = blockIdx.x * 8 + w;

    const float* x0 = g_xnk0 + (size_t)edge * 96;
    const float* x1 = g_xnk1 + (size_t)edge * 96;
    float qv = g_q0[(size_t)edge * 32 + lane] + g_q1[(size_t)edge * 32 + lane];
    float kv = x0[64 + lane] + x1[64 + lane];
    float p  = qv * kv;
#pragma unroll
    for (int off = 16; off > 0; off >>= 1)
        p += __shfl_xor_sync(0xffffffffu, p, off);

    float s = ppr_scores[edge] / (1.f + expf(-p));
    sv[w * 64 + lane]      = (x0[lane]      + x1[lane])      * s;
    sv[w * 64 + 32 + lane] = (x0[32 + lane] + x1[32 + lane]) * s;
    if (lane == 0) sg[w] = ppr_idx[edge];
    __syncthreads();

    if (tid < 64) {
        const int col = tid;
        float accv = sv[col];
        int   g    = sg[0];
#pragma unroll
        for (int w2 = 1; w2 < 8; ++w2) {
            int   g2 = sg[w2];
            float v  = sv[w2 * 64 + col];
            if (g2 == g) {
                accv += v;
            } else {
                atomicAdd(&out[(size_t)g * 64 + col], accv);
                g = g2;
                accv = v;
            }
        }
        atomicAdd(&out[(size_t)g * 64 + col], accv);
    }
}

// ===========================================================================
// Launch sequence (graph-capturable)
// ===========================================================================
extern "C" void kernel_launch(void* const* d_in, const int* in_sizes, int n_in,
                              void* d_out, int out_size) {
    const float* source_attr   = (const float*)d_in[0];
    const float* neighbor_attr = (const float*)d_in[1];
    const float* ppr_scores    = (const float*)d_in[2];
    const int*   ppr_idx       = (const int*)  d_in[3];
    const float* W0  = (const float*)d_in[5];
    const float* W1  = (const float*)d_in[6];
    const float* W2  = (const float*)d_in[7];
    const float* Wqk = (const float*)d_in[8];
    const float* Wk  = (const float*)d_in[9];
    float* out = (float*)d_out;

    __nv_bfloat16 *hiB, *loB;
    __nv_bfloat16 *w0h, *w0l, *w1h, *w1l, *w2qh, *w2ql, *wch, *wcl;
    float *q0, *q1, *x0, *x1;
    cudaGetSymbolAddress((void**)&hiB, g_hiB);
    cudaGetSymbolAddress((void**)&loB, g_loB);
    cudaGetSymbolAddress((void**)&q0, g_q0);
    cudaGetSymbolAddress((void**)&q1, g_q1);
    cudaGetSymbolAddress((void**)&x0, g_xnk0);
    cudaGetSymbolAddress((void**)&x1, g_xnk1);
    cudaGetSymbolAddress((void**)&w0h, g_W0t_hi);
    cudaGetSymbolAddress((void**)&w0l, g_W0t_lo);
    cudaGetSymbolAddress((void**)&w1h, g_W1t_hi);
    cudaGetSymbolAddress((void**)&w1l, g_W1t_lo);
    cudaGetSymbolAddress((void**)&w2qh, g_W2qt_hi);
    cudaGetSymbolAddress((void**)&w2ql, g_W2qt_lo);
    cudaGetSymbolAddress((void**)&wch, g_Wct_hi);
    cudaGetSymbolAddress((void**)&wcl, g_Wct_lo);

    // dynamic smem:
    //  L1  (NSTAGE=3, N3=0):  3*32KB               = 98304
    //  L2q (NSTAGE=2, N3=32): 2*32KB + 32*512  B   = 81920
    //  L2x (NSTAGE=2, N3=96): 2*32KB + 96*512  B   = 114688
    constexpr int SML1  = 3 * 32768;
    constexpr int SML2Q = 2 * 32768 + 32 * 512;
    constexpr int SML2X = 2 * 32768 + 96 * 512;
    cudaFuncSetAttribute((const void*)hmma_gemm<true, 0, true, 3>,
                         cudaFuncAttributeMaxDynamicSharedMemorySize, SML1);
    cudaFuncSetAttribute((const void*)hmma_gemm<false, 32, false, 2>,
                         cudaFuncAttributeMaxDynamicSharedMemorySize, SML2Q);
    cudaFuncSetAttribute((const void*)hmma_gemm<false, 96, false, 2>,
                         cudaFuncAttributeMaxDynamicSharedMemorySize, SML2X);

    const int MB = E_EDGES / 128;  // 3125 row tiles

    prep_fold<<<1, 256>>>(W2, Wqk, Wk);
    prep_transpose_split<<<256, 256>>>(W0, W1);
    cudaMemsetAsync(d_out, 0, (size_t)out_size * sizeof(float));

    // ---- source branch: L1 (fp32 in -> H1 hi/lo), L2+L3 fused -> q partials ----
    hmma_gemm<true, 0, true, 3><<<dim3(MB, 2), 256, SML1>>>(
        source_attr, nullptr, w0h, w0l, nullptr, nullptr, hiB, loB);
    hmma_gemm<false, 32, false, 2><<<dim3(MB, 2), 256, SML2Q>>>(
        hiB, loB, w1h, w1l, w2qh, w2ql, q0, q1);

    // ---- neighbor branch: L2+L3 fused -> [xn|k] partials ----
    hmma_gemm<true, 0, true, 3><<<dim3(MB, 2), 256, SML1>>>(
        neighbor_attr, nullptr, w0h, w0l, nullptr, nullptr, hiB, loB);
    hmma_gemm<false, 96, false, 2><<<dim3(MB, 2), 256, SML2X>>>(
        hiB, loB, w1h, w1l, wch, wcl, x0, x1);

    // ---- attention + segment scatter (8 edges per block) ----
    edge_finalize<<<E_EDGES / 8, 256>>>(ppr_scores, ppr_idx, out);
}

// round 15
// speedup vs baseline: 1.0289x; 1.0289x over previous
#include <cuda_runtime.h>
#include <cuda_bf16.h>
#include <math.h>
#include <stdint.h>

#define E_EDGES 400000
#define NGROUPS 25000

// ===========================================================================
// PTX helpers (sm_80-class only — toolchain targets plain sm_103, no tcgen05)
// ===========================================================================
__device__ __forceinline__ uint32_t smem_u32(const void* p) {
    uint32_t a;
    asm("{ .reg .u64 t; cvta.to.shared.u64 t, %1; cvt.u32.u64 %0, t; }"
        : "=r"(a) : "l"(p));
    return a;
}

#define CP_ASYNC16(sm, gm) \
    asm volatile("cp.async.cg.shared.global [%0], [%1], 16;" \
        :: "r"(sm), "l"(gm) : "memory")
#define CP_COMMIT() asm volatile("cp.async.commit_group;" ::: "memory")
#define CP_WAIT(n)  asm volatile("cp.async.wait_group %0;" :: "n"(n) : "memory")

__device__ __forceinline__ void ldsm_x4(uint32_t* d, uint32_t addr) {
    asm volatile("ldmatrix.sync.aligned.m8n8.x4.shared.b16 {%0,%1,%2,%3}, [%4];"
        : "=r"(d[0]), "=r"(d[1]), "=r"(d[2]), "=r"(d[3]) : "r"(addr));
}

#define MMA16816(d, a, b) \
    asm volatile("mma.sync.aligned.m16n8k16.row.col.f32.bf16.bf16.f32 " \
        "{%0,%1,%2,%3}, {%4,%5,%6,%7}, {%8,%9}, {%0,%1,%2,%3};" \
        : "+f"((d)[0]), "+f"((d)[1]), "+f"((d)[2]), "+f"((d)[3]) \
        : "r"((a)[0]), "r"((a)[1]), "r"((a)[2]), "r"((a)[3]), \
          "r"((b)[0]), "r"((b)[1]))

// SW64 swizzle for 64-byte rows (BK=32 bf16)
__device__ __forceinline__ uint32_t sw(uint32_t off) {
    return off ^ ((off >> 3) & 0x30);
}

// ===========================================================================
// Scratch globals (no cudaMalloc allowed)
// ===========================================================================
__device__ __nv_bfloat16 g_hiB[(size_t)E_EDGES * 256];
__device__ __nv_bfloat16 g_loB[(size_t)E_EDGES * 256];
// fused layer-3 partial outputs (per y-tile, summed in edge_finalize)
__device__ float g_q0  [(size_t)E_EDGES * 32];
__device__ float g_q1  [(size_t)E_EDGES * 32];
__device__ float g_xnk0[(size_t)E_EDGES * 96];
__device__ float g_xnk1[(size_t)E_EDGES * 96];

__device__ float g_W2q [256 * 32];   // W2 @ Wqk  (fp32, [k][n])
__device__ float g_Wcat[256 * 96];   // [W2 | W2@Wk] (fp32, [k][n])
// Transposed + split weights, [n][k] layout (K contiguous)
__device__ __nv_bfloat16 g_W0t_hi[256 * 256], g_W0t_lo[256 * 256];
__device__ __nv_bfloat16 g_W1t_hi[256 * 256], g_W1t_lo[256 * 256];
__device__ __nv_bfloat16 g_W2qt_hi[32 * 256], g_W2qt_lo[32 * 256];
__device__ __nv_bfloat16 g_Wct_hi[96 * 256],  g_Wct_lo[96 * 256];

__device__ __forceinline__ void split2(float v, __nv_bfloat16& h, __nv_bfloat16& l) {
    h = __float2bfloat16_rn(v);
    l = __float2bfloat16_rn(v - __bfloat162float(h));
}

// Packed: (v0,v1) -> hi bf16x2 word + lo bf16x2 word. One cvt per word;
// bf16->f32 for the residual is a pure bit shift.
__device__ __forceinline__ void split2x2(float v0, float v1,
                                         uint32_t& hw, uint32_t& lw) {
    uint32_t h;
    asm("cvt.rn.bf16x2.f32 %0, %1, %2;" : "=r"(h) : "f"(v1), "f"(v0));
    float h0 = __uint_as_float(h << 16);
    float h1 = __uint_as_float(h & 0xffff0000u);
    float l0 = v0 - h0;
    float l1 = v1 - h1;
    asm("cvt.rn.bf16x2.f32 %0, %1, %2;" : "=r"(lw) : "f"(l1), "f"(l0));
    hw = h;
}

// ===========================================================================
// prep1: fold head projections: g_W2q = W2@Wqk, g_Wcat = [W2 | W2@Wk]
// ===========================================================================
__global__ void prep_fold(const float* __restrict__ W2,
                          const float* __restrict__ Wqk,
                          const float* __restrict__ Wk) {
    __shared__ float sQ[64 * 32];
    __shared__ float sK[64 * 32];
    int tid = threadIdx.x;
    for (int i = tid; i < 64 * 32; i += 256) { sQ[i] = Wqk[i]; sK[i] = Wk[i]; }
    __syncthreads();
    int r = tid;
    float w2r[64];
#pragma unroll
    for (int j = 0; j < 64; ++j) w2r[j] = W2[r * 64 + j];
#pragma unroll 4
    for (int c = 0; c < 32; ++c) {
        float aq = 0.f, ak = 0.f;
#pragma unroll
        for (int j = 0; j < 64; ++j) {
            aq = fmaf(w2r[j], sQ[j * 32 + c], aq);
            ak = fmaf(w2r[j], sK[j * 32 + c], ak);
        }
        g_W2q[r * 32 + c]       = aq;
        g_Wcat[r * 96 + 64 + c] = ak;
    }
#pragma unroll
    for (int j = 0; j < 64; ++j) g_Wcat[r * 96 + j] = w2r[j];
}

// ===========================================================================
// prep2: transpose to [n][k] and split all GEMM weights to bf16 hi/lo
// ===========================================================================
__global__ void prep_transpose_split(const float* __restrict__ W0,
                                     const float* __restrict__ W1) {
    int t = blockIdx.x * 256 + threadIdx.x;
    int o = t >> 8, i = t & 255;
    __nv_bfloat16 h, l;
    split2(W0[i * 256 + o], h, l);  g_W0t_hi[t] = h;  g_W0t_lo[t] = l;
    split2(W1[i * 256 + o], h, l);  g_W1t_hi[t] = h;  g_W1t_lo[t] = l;
    if (o < 32) { split2(g_W2q[i * 32 + o], h, l);  g_W2qt_hi[t] = h; g_W2qt_lo[t] = l; }
    if (o < 96) { split2(g_Wcat[i * 96 + o], h, l); g_Wct_hi[t] = h;  g_Wct_lo[t] = l; }
}

// ===========================================================================
// HMMA GEMM, bf16x3: C = Ah*Bh + Al*Bh + Ah*Bl.
// BM=128, BN=128, BK=32, 8 K-chunks, 2-stage double buffer (measured faster
// than 3-stage on this chip across R8/R9/R14).
// 256 threads = 8 warps (4M x 2N); warp = 32 rows x 64 cols (NB=8 n8-tiles).
//
// FP32A:      A fp32 in gmem; LDG prefetch at iteration top (hidden under the
//             MMA section), packed split + STS after compute, before the
//             trailing barrier.
// SPLIT_RELU: epilogue = relu + packed re-split hi/lo bf16 (feeds L2).
// N3 > 0:     FUSED LAYER-3. W3 slice prefetched in the PROLOGUE into a
//             dedicated smem region; epilogue = P-stage + 1 barrier + 8
//             uninterrupted ldsm/MMA iterations. Partial -> out0/out1 by y.
// ===========================================================================
template <bool SPLIT_RELU, int N3, bool FP32A>
__global__ void __launch_bounds__(256, 2)
hmma_gemm(const void* __restrict__ Ah_, const __nv_bfloat16* __restrict__ Al,
          const __nv_bfloat16* __restrict__ Bh, const __nv_bfloat16* __restrict__ Bl,
          const __nv_bfloat16* __restrict__ W3h, const __nv_bfloat16* __restrict__ W3l,
          void* __restrict__ out0, void* __restrict__ out1) {
    constexpr int BN    = 128;
    constexpr int NB    = 8;                 // n8-tiles per warp = 64 cols
    constexpr int A_CH  = 128 * 64;          // bytes per A split per chunk
    constexpr int B_CH  = BN * 64;
    constexpr int STAGE = 2 * A_CH + 2 * B_CH;   // 32 KB

    extern __shared__ char smem[];
    const uint32_t s0 = smem_u32(smem);
    const uint32_t w3off = s0 + 2 * STAGE;   // W3 region (N3>0 only)

    const int tid  = threadIdx.x;
    const int lane = tid & 31;
    const int wid  = tid >> 5;
    const int m0w  = (wid & 3) * 32;
    const int n0w  = (wid >> 2) * 64;
    const int row0 = blockIdx.x * 128;
    const int col0 = blockIdx.y * BN;

    const float* Afp = (const float*)Ah_;
    const __nv_bfloat16* Ah = (const __nv_bfloat16*)Ah_;

    float acc[2][NB][4];
#pragma unroll
    for (int mi = 0; mi < 2; ++mi)
#pragma unroll
        for (int ni = 0; ni < NB; ++ni)
#pragma unroll
            for (int v = 0; v < 4; ++v) acc[mi][ni][v] = 0.f;

    float4 pf[4];  // FP32A prefetch

    auto loadB = [&](int c, int buf) {
        const int kk = c << 5;
#pragma unroll
        for (int i = tid; i < 2 * BN * 4; i += 256) {
            int sp = i / (BN * 4), idx = i % (BN * 4), n = idx >> 2, g = idx & 3;
            const __nv_bfloat16* src =
                (sp ? Bl : Bh) + (size_t)(col0 + n) * 256 + kk + g * 8;
            CP_ASYNC16(s0 + buf * STAGE + 2 * A_CH + sp * B_CH + sw(n * 64 + g * 16), src);
        }
    };
    auto loadA_cp = [&](int c, int buf) {
        const int kk = c << 5;
#pragma unroll
        for (int i = tid; i < 1024; i += 256) {
            int sp = i >> 9, idx = i & 511, r = idx >> 2, g = idx & 3;
            const __nv_bfloat16* src =
                (sp ? Al : Ah) + (size_t)(row0 + r) * 256 + kk + g * 8;
            CP_ASYNC16(s0 + buf * STAGE + sp * A_CH + sw(r * 64 + g * 16), src);
        }
    };
    auto ldA_f32 = [&](int c) {
        const int kk = c << 5;
#pragma unroll
        for (int j = 0; j < 4; ++j) {
            int f4 = tid + 256 * j;
            int r = f4 >> 3, c4 = f4 & 7;
            pf[j] = *(const float4*)(Afp + (size_t)(row0 + r) * 256 + kk + c4 * 4);
        }
    };
    auto stA_f32 = [&](int buf) {
#pragma unroll
        for (int j = 0; j < 4; ++j) {
            int f4 = tid + 256 * j;
            int r = f4 >> 3, c4 = f4 & 7;
            uint2 hw, lw;
            split2x2(pf[j].x, pf[j].y, hw.x, lw.x);
            split2x2(pf[j].z, pf[j].w, hw.y, lw.y);
            uint32_t off = buf * STAGE + sw(r * 64 + c4 * 8);
            *(uint2*)(smem + off)        = hw;
            *(uint2*)(smem + off + A_CH) = lw;
        }
    };

    auto computeChunk = [&](uint32_t st) {
        const uint32_t da = st;
        const uint32_t db = st + 2 * A_CH;
#pragma unroll
        for (int ks = 0; ks < 2; ++ks) {
            uint32_t ah[2][4], al[2][4];
#pragma unroll
            for (int mi = 0; mi < 2; ++mi) {
                uint32_t aoff = sw((m0w + mi * 16 + (lane & 15)) * 64 +
                                   ks * 32 + (lane >> 4) * 16);
                ldsm_x4(ah[mi], da + aoff);
                ldsm_x4(al[mi], da + A_CH + aoff);
            }
            uint32_t bh[NB][2], bl[NB][2];
#pragma unroll
            for (int np = 0; np < NB / 2; ++np) {
                uint32_t boff = sw((n0w + np * 16 + (lane >> 4) * 8 + (lane & 7)) * 64 +
                                   ks * 32 + ((lane >> 3) & 1) * 16);
                ldsm_x4(&bh[2 * np][0], db + boff);
                ldsm_x4(&bl[2 * np][0], db + B_CH + boff);
            }
#pragma unroll
            for (int mi = 0; mi < 2; ++mi)
#pragma unroll
                for (int ni = 0; ni < NB; ++ni)
                    MMA16816(acc[mi][ni], ah[mi], bh[ni]);
#pragma unroll
            for (int mi = 0; mi < 2; ++mi)
#pragma unroll
                for (int ni = 0; ni < NB; ++ni)
                    MMA16816(acc[mi][ni], al[mi], bh[ni]);
#pragma unroll
            for (int mi = 0; mi < 2; ++mi)
#pragma unroll
                for (int ni = 0; ni < NB; ++ni)
                    MMA16816(acc[mi][ni], ah[mi], bl[ni]);
        }
    };

    // ---- prologue ----
    if constexpr (N3 > 0) {
        // W3 prefetch: first commit group; resident through the mainloop.
#pragma unroll
        for (int i = tid; i < 2 * 4 * N3 * 4; i += 256) {
            int sp = i / (4 * N3 * 4), r1 = i % (4 * N3 * 4);
            int kc = r1 / (N3 * 4),   r2 = r1 % (N3 * 4);
            int n  = r2 >> 2,         g  = r2 & 3;
            const __nv_bfloat16* src =
                (sp ? W3l : W3h) + (size_t)n * 256 + col0 + kc * 32 + g * 8;
            CP_ASYNC16(w3off + (sp * 4 + kc) * (N3 * 64) + sw(n * 64 + g * 16), src);
        }
        CP_COMMIT();
    }

    if (FP32A) {
        ldA_f32(0); stA_f32(0);
        loadB(0, 0); CP_COMMIT();
    } else {
        loadA_cp(0, 0); loadB(0, 0); CP_COMMIT();
    }

#pragma unroll 1
    for (int c = 0; c < 8; ++c) {
        if (c < 7) {
            if (FP32A) {
                ldA_f32(c + 1);                 // LDG latency hidden under MMAs
                loadB(c + 1, (c + 1) & 1);
            } else {
                loadA_cp(c + 1, (c + 1) & 1);
                loadB(c + 1, (c + 1) & 1);
            }
            CP_COMMIT();
            CP_WAIT(1);
        } else {
            CP_WAIT(0);
        }
        __syncthreads();
        computeChunk(s0 + (c & 1) * STAGE);
        if (FP32A && c < 7) stA_f32((c + 1) & 1);  // buffer free: readers passed 1st barrier
        __syncthreads();
    }

    // =======================================================================
    // Epilogues (compile-time selected)
    // =======================================================================
    if constexpr (SPLIT_RELU) {
        const int rbase = row0 + m0w + (lane >> 2);
        __nv_bfloat16* hi = (__nv_bfloat16*)out0;
        __nv_bfloat16* lo = (__nv_bfloat16*)out1;
#pragma unroll
        for (int mi = 0; mi < 2; ++mi) {
            const int r0 = rbase + mi * 16;
#pragma unroll
            for (int ni = 0; ni < NB; ++ni) {
                const int c = col0 + n0w + ni * 8 + (lane & 3) * 2;
#pragma unroll
                for (int h = 0; h < 2; ++h) {
                    float v0 = fmaxf(acc[mi][ni][2 * h],     0.f);
                    float v1 = fmaxf(acc[mi][ni][2 * h + 1], 0.f);
                    uint32_t hw, lw;
                    split2x2(v0, v1, hw, lw);
                    size_t off = (size_t)(r0 + h * 8) * 256 + c;
                    *(uint32_t*)(hi + off) = hw;
                    *(uint32_t*)(lo + off) = lw;
                }
            }
        }
    }

    if constexpr (N3 > 0) {
        // ---- fused layer-3: G = relu(H2_tile) @ W3t[:, col0:col0+128]^T ----
        constexpr int NT3   = N3 / 8;        // n8-tiles per warp
        constexpr int PH_SZ = 128 * 64;      // one K=32 chunk of P per split
        const uint32_t pH = s0;              // 4 chunks (overlays stage bufs)
        const uint32_t pL = s0 + 4 * PH_SZ;

        __syncthreads();   // all mainloop smem reads finished; stage smem free

        // stage FULL P tile (this warp's 64 cols, rows it owns)
#pragma unroll
        for (int mi = 0; mi < 2; ++mi)
#pragma unroll
            for (int ni = 0; ni < NB; ++ni) {
                const int cl = n0w + ni * 8 + (lane & 3) * 2;  // col within 128
                const int j  = cl >> 5;
                const int cc = cl & 31;
#pragma unroll
                for (int rr = 0; rr < 2; ++rr) {
                    const int r = m0w + mi * 16 + (lane >> 2) + rr * 8;
                    float v0 = fmaxf(acc[mi][ni][2 * rr],     0.f);
                    float v1 = fmaxf(acc[mi][ni][2 * rr + 1], 0.f);
                    uint32_t hw, lw;
                    split2x2(v0, v1, hw, lw);
                    uint32_t off = j * PH_SZ + sw(r * 64 + cc * 2);
                    *(uint32_t*)(smem + off)             = hw;
                    *(uint32_t*)(smem + 4 * PH_SZ + off) = lw;
                }
            }

        float acc2[NT3][4];
#pragma unroll
        for (int ni = 0; ni < NT3; ++ni)
#pragma unroll
            for (int v = 0; v < 4; ++v) acc2[ni][v] = 0.f;

        __syncthreads();   // P visible; W3 already resident since prologue

#pragma unroll
        for (int jg = 0; jg < 4; ++jg) {
#pragma unroll
            for (int ks2 = 0; ks2 < 2; ++ks2) {
                uint32_t ph4[4], pl4[4];
                uint32_t aoff = jg * PH_SZ +
                                sw((wid * 16 + (lane & 15)) * 64 +
                                   ks2 * 32 + (lane >> 4) * 16);
                ldsm_x4(ph4, pH + aoff);
                ldsm_x4(pl4, pL + aoff);
                uint32_t w3h[NT3][2], w3l[NT3][2];
#pragma unroll
                for (int np2 = 0; np2 < NT3 / 2; ++np2) {
                    uint32_t rowoff = sw((np2 * 16 + (lane >> 4) * 8 + (lane & 7)) * 64 +
                                         ks2 * 32 + ((lane >> 3) & 1) * 16);
                    ldsm_x4(&w3h[2 * np2][0], w3off + jg * (N3 * 64) + rowoff);
                    ldsm_x4(&w3l[2 * np2][0], w3off + (4 + jg) * (N3 * 64) + rowoff);
                }
#pragma unroll
                for (int ni = 0; ni < NT3; ++ni) MMA16816(acc2[ni], ph4, w3h[ni]);
#pragma unroll
                for (int ni = 0; ni < NT3; ++ni) MMA16816(acc2[ni], pl4, w3h[ni]);
#pragma unroll
                for (int ni = 0; ni < NT3; ++ni) MMA16816(acc2[ni], ph4, w3l[ni]);
            }
        }

        // store fp32 partial [128, N3] to the per-y buffer
        float* op = (float*)(blockIdx.y ? out1 : out0);
        const int r0 = row0 + wid * 16 + (lane >> 2);
#pragma unroll
        for (int ni = 0; ni < NT3; ++ni) {
            const int c = ni * 8 + (lane & 3) * 2;
            *(float2*)(op + (size_t)r0 * N3 + c) =
                make_float2(acc2[ni][0], acc2[ni][1]);
            *(float2*)(op + (size_t)(r0 + 8) * N3 + c) =
                make_float2(acc2[ni][2], acc2[ni][3]);
        }
    }
}

// ===========================================================================
// Edge finalize: one warp per edge (reverted to the R13 form — the R14
// run-compression regressed). Sums the two layer-3 partials.
//   s = sigmoid(dot(q,k)) * ppr;  atomicAdd(out[ppr_idx][:], xn[:] * s)
// ===========================================================================
__global__ void edge_finalize(const float* __restrict__ ppr_scores,
                              const int* __restrict__ ppr_idx,
                              float* __restrict__ out) {
    int gtid = blockIdx.x * blockDim.x + threadIdx.x;
    int edge = gtid >> 5;
    int lane = gtid & 31;
    if (edge >= E_EDGES) return;

    const float* x0 = g_xnk0 + (size_t)edge * 96;
    const float* x1 = g_xnk1 + (size_t)edge * 96;
    float qv = g_q0[(size_t)edge * 32 + lane] + g_q1[(size_t)edge * 32 + lane];
    float kv = x0[64 + lane] + x1[64 + lane];
    float p  = qv * kv;
#pragma unroll
    for (int off = 16; off > 0; off >>= 1)
        p += __shfl_xor_sync(0xffffffffu, p, off);

    float s = ppr_scores[edge] / (1.f + expf(-p));
    int g = ppr_idx[edge];
    float v0 = (x0[lane]      + x1[lane])      * s;
    float v1 = (x0[32 + lane] + x1[32 + lane]) * s;
    atomicAdd(&out[(size_t)g * 64 + lane],      v0);
    atomicAdd(&out[(size_t)g * 64 + 32 + lane], v1);
}

// ===========================================================================
// Launch sequence (graph-capturable)
// ===========================================================================
extern "C" void kernel_launch(void* const* d_in, const int* in_sizes, int n_in,
                              void* d_out, int out_size) {
    const float* source_attr   = (const float*)d_in[0];
    const float* neighbor_attr = (const float*)d_in[1];
    const float* ppr_scores    = (const float*)d_in[2];
    const int*   ppr_idx       = (const int*)  d_in[3];
    const float* W0  = (const float*)d_in[5];
    const float* W1  = (const float*)d_in[6];
    const float* W2  = (const float*)d_in[7];
    const float* Wqk = (const float*)d_in[8];
    const float* Wk  = (const float*)d_in[9];
    float* out = (float*)d_out;

    __nv_bfloat16 *hiB, *loB;
    __nv_bfloat16 *w0h, *w0l, *w1h, *w1l, *w2qh, *w2ql, *wch, *wcl;
    float *q0, *q1, *x0, *x1;
    cudaGetSymbolAddress((void**)&hiB, g_hiB);
    cudaGetSymbolAddress((void**)&loB, g_loB);
    cudaGetSymbolAddress((void**)&q0, g_q0);
    cudaGetSymbolAddress((void**)&q1, g_q1);
    cudaGetSymbolAddress((void**)&x0, g_xnk0);
    cudaGetSymbolAddress((void**)&x1, g_xnk1);
    cudaGetSymbolAddress((void**)&w0h, g_W0t_hi);
    cudaGetSymbolAddress((void**)&w0l, g_W0t_lo);
    cudaGetSymbolAddress((void**)&w1h, g_W1t_hi);
    cudaGetSymbolAddress((void**)&w1l, g_W1t_lo);
    cudaGetSymbolAddress((void**)&w2qh, g_W2qt_hi);
    cudaGetSymbolAddress((void**)&w2ql, g_W2qt_lo);
    cudaGetSymbolAddress((void**)&wch, g_Wct_hi);
    cudaGetSymbolAddress((void**)&wcl, g_Wct_lo);

    // dynamic smem:
    //  L1  (N3=0):   2*32KB              = 65536
    //  L2q (N3=32):  2*32KB + 32*512 B   = 81920
    //  L2x (N3=96):  2*32KB + 96*512 B   = 114688
    constexpr int SML1  = 2 * 32768;
    constexpr int SML2Q = 2 * 32768 + 32 * 512;
    constexpr int SML2X = 2 * 32768 + 96 * 512;
    cudaFuncSetAttribute((const void*)hmma_gemm<true, 0, true>,
                         cudaFuncAttributeMaxDynamicSharedMemorySize, SML1);
    cudaFuncSetAttribute((const void*)hmma_gemm<false, 32, false>,
                         cudaFuncAttributeMaxDynamicSharedMemorySize, SML2Q);
    cudaFuncSetAttribute((const void*)hmma_gemm<false, 96, false>,
                         cudaFuncAttributeMaxDynamicSharedMemorySize, SML2X);

    const int MB = E_EDGES / 128;  // 3125 row tiles

    prep_fold<<<1, 256>>>(W2, Wqk, Wk);
    prep_transpose_split<<<256, 256>>>(W0, W1);
    cudaMemsetAsync(d_out, 0, (size_t)out_size * sizeof(float));

    // ---- source branch: L1 (fp32 in -> H1 hi/lo), L2+L3 fused -> q partials ----
    hmma_gemm<true, 0, true><<<dim3(MB, 2), 256, SML1>>>(
        source_attr, nullptr, w0h, w0l, nullptr, nullptr, hiB, loB);
    hmma_gemm<false, 32, false><<<dim3(MB, 2), 256, SML2Q>>>(
        hiB, loB, w1h, w1l, w2qh, w2ql, q0, q1);

    // ---- neighbor branch: L2+L3 fused -> [xn|k] partials ----
    hmma_gemm<true, 0, true><<<dim3(MB, 2), 256, SML1>>>(
        neighbor_attr, nullptr, w0h, w0l, nullptr, nullptr, hiB, loB);
    hmma_gemm<false, 96, false><<<dim3(MB, 2), 256, SML2X>>>(
        hiB, loB, w1h, w1l, wch, wcl, x0, x1);

    // ---- attention + segment scatter ----
    edge_finalize<<<(E_EDGES * 32 + 255) / 256, 256>>>(ppr_scores, ppr_idx, out);
}

// round 16
// speedup vs baseline: 1.4626x; 1.4216x over previous
#include <cuda_runtime.h>
#include <cuda_fp16.h>
#include <math.h>
#include <stdint.h>

#define E_EDGES 400000
#define NGROUPS 25000

// ===========================================================================
// PTX helpers (sm_80-class only — toolchain targets plain sm_103, no tcgen05)
// ===========================================================================
__device__ __forceinline__ uint32_t smem_u32(const void* p) {
    uint32_t a;
    asm("{ .reg .u64 t; cvta.to.shared.u64 t, %1; cvt.u32.u64 %0, t; }"
        : "=r"(a) : "l"(p));
    return a;
}

#define CP_ASYNC16(sm, gm) \
    asm volatile("cp.async.cg.shared.global [%0], [%1], 16;" \
        :: "r"(sm), "l"(gm) : "memory")
#define CP_COMMIT() asm volatile("cp.async.commit_group;" ::: "memory")
#define CP_WAIT(n)  asm volatile("cp.async.wait_group %0;" :: "n"(n) : "memory")

__device__ __forceinline__ void ldsm_x4(uint32_t* d, uint32_t addr) {
    asm volatile("ldmatrix.sync.aligned.m8n8.x4.shared.b16 {%0,%1,%2,%3}, [%4];"
        : "=r"(d[0]), "=r"(d[1]), "=r"(d[2]), "=r"(d[3]) : "r"(addr));
}

// fp16 in, fp32 accumulate
#define MMA16816(d, a, b) \
    asm volatile("mma.sync.aligned.m16n8k16.row.col.f32.f16.f16.f32 " \
        "{%0,%1,%2,%3}, {%4,%5,%6,%7}, {%8,%9}, {%0,%1,%2,%3};" \
        : "+f"((d)[0]), "+f"((d)[1]), "+f"((d)[2]), "+f"((d)[3]) \
        : "r"((a)[0]), "r"((a)[1]), "r"((a)[2]), "r"((a)[3]), \
          "r"((b)[0]), "r"((b)[1]))

// SW64 swizzle for 64-byte rows (BK=32 fp16)
__device__ __forceinline__ uint32_t sw(uint32_t off) {
    return off ^ ((off >> 3) & 0x30);
}

// ===========================================================================
// Scratch globals (no cudaMalloc allowed)
// ===========================================================================
__device__ __half g_H1[(size_t)E_EDGES * 256];     // H1, single fp16
// fused layer-3 partial outputs (per y-tile, summed in edge_finalize)
__device__ float g_q0  [(size_t)E_EDGES * 32];
__device__ float g_q1  [(size_t)E_EDGES * 32];
__device__ float g_xnk0[(size_t)E_EDGES * 96];
__device__ float g_xnk1[(size_t)E_EDGES * 96];

__device__ float g_W2q [256 * 32];   // W2 @ Wqk  (fp32, [k][n])
__device__ float g_Wcat[256 * 96];   // [W2 | W2@Wk] (fp32, [k][n])
// Transposed weights, [n][k] layout (K contiguous), fp16
__device__ __half g_W0t   [256 * 256];                  // single (B of L1)
__device__ __half g_W1t_hi[256 * 256], g_W1t_lo[256 * 256];
__device__ __half g_W2qt_hi[32 * 256], g_W2qt_lo[32 * 256];
__device__ __half g_Wct_hi[96 * 256],  g_Wct_lo[96 * 256];

__device__ __forceinline__ void hsplit(float v, __half& h, __half& l) {
    h = __float2half_rn(v);
    l = __float2half_rn(v - __half2float(h));
}

// Packed: (v0,v1) -> hi f16x2 word + lo f16x2 word.
__device__ __forceinline__ void hsplit2x2(float v0, float v1,
                                          uint32_t& hw, uint32_t& lw) {
    asm("cvt.rn.f16x2.f32 %0, %1, %2;" : "=r"(hw) : "f"(v1), "f"(v0));
    __half2 hh = *reinterpret_cast<__half2*>(&hw);
    float2 hf = __half22float2(hh);
    asm("cvt.rn.f16x2.f32 %0, %1, %2;" : "=r"(lw) : "f"(v1 - hf.y), "f"(v0 - hf.x));
}

__device__ __forceinline__ uint32_t hpack(float v0, float v1) {
    uint32_t w;
    asm("cvt.rn.f16x2.f32 %0, %1, %2;" : "=r"(w) : "f"(v1), "f"(v0));
    return w;
}

// ===========================================================================
// prep1: fold head projections: g_W2q = W2@Wqk, g_Wcat = [W2 | W2@Wk]
// ===========================================================================
__global__ void prep_fold(const float* __restrict__ W2,
                          const float* __restrict__ Wqk,
                          const float* __restrict__ Wk) {
    __shared__ float sQ[64 * 32];
    __shared__ float sK[64 * 32];
    int tid = threadIdx.x;
    for (int i = tid; i < 64 * 32; i += 256) { sQ[i] = Wqk[i]; sK[i] = Wk[i]; }
    __syncthreads();
    int r = tid;
    float w2r[64];
#pragma unroll
    for (int j = 0; j < 64; ++j) w2r[j] = W2[r * 64 + j];
#pragma unroll 4
    for (int c = 0; c < 32; ++c) {
        float aq = 0.f, ak = 0.f;
#pragma unroll
        for (int j = 0; j < 64; ++j) {
            aq = fmaf(w2r[j], sQ[j * 32 + c], aq);
            ak = fmaf(w2r[j], sK[j * 32 + c], ak);
        }
        g_W2q[r * 32 + c]       = aq;
        g_Wcat[r * 96 + 64 + c] = ak;
    }
#pragma unroll
    for (int j = 0; j < 64; ++j) g_Wcat[r * 96 + j] = w2r[j];
}

// ===========================================================================
// prep2: transpose to [n][k]; W0 single fp16, others split fp16 hi/lo
// ===========================================================================
__global__ void prep_transpose_split(const float* __restrict__ W0,
                                     const float* __restrict__ W1) {
    int t = blockIdx.x * 256 + threadIdx.x;
    int o = t >> 8, i = t & 255;
    __half h, l;
    g_W0t[t] = __float2half_rn(W0[i * 256 + o]);
    hsplit(W1[i * 256 + o], h, l);  g_W1t_hi[t] = h;  g_W1t_lo[t] = l;
    if (o < 32) { hsplit(g_W2q[i * 32 + o], h, l);  g_W2qt_hi[t] = h; g_W2qt_lo[t] = l; }
    if (o < 96) { hsplit(g_Wcat[i * 96 + o], h, l); g_Wct_hi[t] = h;  g_Wct_lo[t] = l; }
}

// ===========================================================================
// L1 GEMM (fp16x2, A split / B single):
//   H1 = relu( X @ W0 ),  computed as Xh*W0h + Xl*W0h  (W0h = fp16(W0))
// A = X fp32 in gmem: LDG prefetch + in-register split + STS (FP32A path).
// BM=128, BN=128, BK=32, 8 chunks, 2-stage. Stage = Ah(8K)+Al(8K)+B(8K)=24KB.
// Epilogue: relu + single fp16 store (width 256).
// ===========================================================================
__global__ void __launch_bounds__(256, 2)
gemm_l1(const float* __restrict__ Afp, const __half* __restrict__ Bw,
        __half* __restrict__ outH) {
    constexpr int BN    = 128;
    constexpr int NB    = 8;
    constexpr int A_CH  = 128 * 64;
    constexpr int B_CH  = BN * 64;
    constexpr int STAGE = 2 * A_CH + B_CH;   // 24 KB

    extern __shared__ char smem[];
    const uint32_t s0 = smem_u32(smem);

    const int tid  = threadIdx.x;
    const int lane = tid & 31;
    const int wid  = tid >> 5;
    const int m0w  = (wid & 3) * 32;
    const int n0w  = (wid >> 2) * 64;
    const int row0 = blockIdx.x * 128;
    const int col0 = blockIdx.y * BN;

    float acc[2][NB][4];
#pragma unroll
    for (int mi = 0; mi < 2; ++mi)
#pragma unroll
        for (int ni = 0; ni < NB; ++ni)
#pragma unroll
            for (int v = 0; v < 4; ++v) acc[mi][ni][v] = 0.f;

    float4 pf[4];

    auto loadB = [&](int c, int buf) {
        const int kk = c << 5;
#pragma unroll
        for (int i = tid; i < BN * 4; i += 256) {
            int n = i >> 2, g = i & 3;
            const __half* src = Bw + (size_t)(col0 + n) * 256 + kk + g * 8;
            CP_ASYNC16(s0 + buf * STAGE + 2 * A_CH + sw(n * 64 + g * 16), src);
        }
    };
    auto ldA_f32 = [&](int c) {
        const int kk = c << 5;
#pragma unroll
        for (int j = 0; j < 4; ++j) {
            int f4 = tid + 256 * j;
            int r = f4 >> 3, c4 = f4 & 7;
            pf[j] = *(const float4*)(Afp + (size_t)(row0 + r) * 256 + kk + c4 * 4);
        }
    };
    auto stA_f32 = [&](int buf) {
#pragma unroll
        for (int j = 0; j < 4; ++j) {
            int f4 = tid + 256 * j;
            int r = f4 >> 3, c4 = f4 & 7;
            uint2 hw, lw;
            hsplit2x2(pf[j].x, pf[j].y, hw.x, lw.x);
            hsplit2x2(pf[j].z, pf[j].w, hw.y, lw.y);
            uint32_t off = buf * STAGE + sw(r * 64 + c4 * 8);
            *(uint2*)(smem + off)        = hw;
            *(uint2*)(smem + off + A_CH) = lw;
        }
    };

    ldA_f32(0); stA_f32(0);
    loadB(0, 0); CP_COMMIT();

#pragma unroll 1
    for (int c = 0; c < 8; ++c) {
        if (c < 7) {
            ldA_f32(c + 1);
            loadB(c + 1, (c + 1) & 1);
            CP_COMMIT();
            CP_WAIT(1);
        } else {
            CP_WAIT(0);
        }
        __syncthreads();

        const uint32_t st = s0 + (c & 1) * STAGE;
        const uint32_t db = st + 2 * A_CH;
#pragma unroll
        for (int ks = 0; ks < 2; ++ks) {
            uint32_t ah[2][4], al[2][4];
#pragma unroll
            for (int mi = 0; mi < 2; ++mi) {
                uint32_t aoff = sw((m0w + mi * 16 + (lane & 15)) * 64 +
                                   ks * 32 + (lane >> 4) * 16);
                ldsm_x4(ah[mi], st + aoff);
                ldsm_x4(al[mi], st + A_CH + aoff);
            }
            uint32_t bh[NB][2];
#pragma unroll
            for (int np = 0; np < NB / 2; ++np) {
                uint32_t boff = sw((n0w + np * 16 + (lane >> 4) * 8 + (lane & 7)) * 64 +
                                   ks * 32 + ((lane >> 3) & 1) * 16);
                ldsm_x4(&bh[2 * np][0], db + boff);
            }
#pragma unroll
            for (int mi = 0; mi < 2; ++mi)
#pragma unroll
                for (int ni = 0; ni < NB; ++ni)
                    MMA16816(acc[mi][ni], ah[mi], bh[ni]);
#pragma unroll
            for (int mi = 0; mi < 2; ++mi)
#pragma unroll
                for (int ni = 0; ni < NB; ++ni)
                    MMA16816(acc[mi][ni], al[mi], bh[ni]);
        }
        if (c < 7) stA_f32((c + 1) & 1);
        __syncthreads();
    }

    // epilogue: relu + single fp16
    const int rbase = row0 + m0w + (lane >> 2);
#pragma unroll
    for (int mi = 0; mi < 2; ++mi) {
        const int r0 = rbase + mi * 16;
#pragma unroll
        for (int ni = 0; ni < NB; ++ni) {
            const int c = col0 + n0w + ni * 8 + (lane & 3) * 2;
#pragma unroll
            for (int h = 0; h < 2; ++h) {
                float v0 = fmaxf(acc[mi][ni][2 * h],     0.f);
                float v1 = fmaxf(acc[mi][ni][2 * h + 1], 0.f);
                *(uint32_t*)(outH + (size_t)(r0 + h * 8) * 256 + c) = hpack(v0, v1);
            }
        }
    }
}

// ===========================================================================
// L2 GEMM + fused L3 (fp16x2, A single / B split):
//   H2 = relu( H1 @ W1 ) = relu( A*W1h + A*W1l ),  A = H1 fp16
//   G  = relu(H2)_fp16 @ (W3h + W3l)  -> fp32 partial per y-tile
// Stage = A(8K)+Bh(8K)+Bl(8K)=24KB, 2 stages. W3 prefetched in prologue.
// ===========================================================================
template <int N3>
__global__ void __launch_bounds__(256, 2)
gemm_l2(const __half* __restrict__ Ain,
        const __half* __restrict__ Bh_, const __half* __restrict__ Bl_,
        const __half* __restrict__ W3h, const __half* __restrict__ W3l,
        float* __restrict__ out0, float* __restrict__ out1) {
    constexpr int BN    = 128;
    constexpr int NB    = 8;
    constexpr int A_CH  = 128 * 64;
    constexpr int B_CH  = BN * 64;
    constexpr int STAGE = A_CH + 2 * B_CH;   // 24 KB

    extern __shared__ char smem[];
    const uint32_t s0 = smem_u32(smem);
    const uint32_t w3off = s0 + 2 * STAGE;

    const int tid  = threadIdx.x;
    const int lane = tid & 31;
    const int wid  = tid >> 5;
    const int m0w  = (wid & 3) * 32;
    const int n0w  = (wid >> 2) * 64;
    const int row0 = blockIdx.x * 128;
    const int col0 = blockIdx.y * BN;

    float acc[2][NB][4];
#pragma unroll
    for (int mi = 0; mi < 2; ++mi)
#pragma unroll
        for (int ni = 0; ni < NB; ++ni)
#pragma unroll
            for (int v = 0; v < 4; ++v) acc[mi][ni][v] = 0.f;

    auto loadA = [&](int c, int buf) {
        const int kk = c << 5;
#pragma unroll
        for (int i = tid; i < 512; i += 256) {
            int r = i >> 2, g = i & 3;
            const __half* src = Ain + (size_t)(row0 + r) * 256 + kk + g * 8;
            CP_ASYNC16(s0 + buf * STAGE + sw(r * 64 + g * 16), src);
        }
    };
    auto loadB = [&](int c, int buf) {
        const int kk = c << 5;
#pragma unroll
        for (int i = tid; i < 2 * BN * 4; i += 256) {
            int sp = i / (BN * 4), idx = i % (BN * 4), n = idx >> 2, g = idx & 3;
            const __half* src =
                (sp ? Bl_ : Bh_) + (size_t)(col0 + n) * 256 + kk + g * 8;
            CP_ASYNC16(s0 + buf * STAGE + A_CH + sp * B_CH + sw(n * 64 + g * 16), src);
        }
    };

    // ---- prologue: W3 prefetch (resident through mainloop), then chunk 0 ----
#pragma unroll
    for (int i = tid; i < 2 * 4 * N3 * 4; i += 256) {
        int sp = i / (4 * N3 * 4), r1 = i % (4 * N3 * 4);
        int kc = r1 / (N3 * 4),   r2 = r1 % (N3 * 4);
        int n  = r2 >> 2,         g  = r2 & 3;
        const __half* src =
            (sp ? W3l : W3h) + (size_t)n * 256 + col0 + kc * 32 + g * 8;
        CP_ASYNC16(w3off + (sp * 4 + kc) * (N3 * 64) + sw(n * 64 + g * 16), src);
    }
    CP_COMMIT();
    loadA(0, 0); loadB(0, 0); CP_COMMIT();

#pragma unroll 1
    for (int c = 0; c < 8; ++c) {
        if (c < 7) {
            loadA(c + 1, (c + 1) & 1);
            loadB(c + 1, (c + 1) & 1);
            CP_COMMIT();
            CP_WAIT(1);
        } else {
            CP_WAIT(0);
        }
        __syncthreads();

        const uint32_t st = s0 + (c & 1) * STAGE;
        const uint32_t db = st + A_CH;
#pragma unroll
        for (int ks = 0; ks < 2; ++ks) {
            uint32_t ah[2][4];
#pragma unroll
            for (int mi = 0; mi < 2; ++mi) {
                uint32_t aoff = sw((m0w + mi * 16 + (lane & 15)) * 64 +
                                   ks * 32 + (lane >> 4) * 16);
                ldsm_x4(ah[mi], st + aoff);
            }
            uint32_t bh[NB][2], bl[NB][2];
#pragma unroll
            for (int np = 0; np < NB / 2; ++np) {
                uint32_t boff = sw((n0w + np * 16 + (lane >> 4) * 8 + (lane & 7)) * 64 +
                                   ks * 32 + ((lane >> 3) & 1) * 16);
                ldsm_x4(&bh[2 * np][0], db + boff);
                ldsm_x4(&bl[2 * np][0], db + B_CH + boff);
            }
#pragma unroll
            for (int mi = 0; mi < 2; ++mi)
#pragma unroll
                for (int ni = 0; ni < NB; ++ni)
                    MMA16816(acc[mi][ni], ah[mi], bh[ni]);
#pragma unroll
            for (int mi = 0; mi < 2; ++mi)
#pragma unroll
                for (int ni = 0; ni < NB; ++ni)
                    MMA16816(acc[mi][ni], ah[mi], bl[ni]);
        }
        __syncthreads();
    }

    // ---- fused layer-3 ----
    constexpr int NT3   = N3 / 8;
    constexpr int PH_SZ = 128 * 64;      // one K=32 chunk of P, fp16 single
    // P region overlays stage buffers (4 chunks x 8KB = 32KB <= 48KB)

    // stage P tile (this warp's 64 cols, rows it owns), relu + single fp16
#pragma unroll
    for (int mi = 0; mi < 2; ++mi)
#pragma unroll
        for (int ni = 0; ni < NB; ++ni) {
            const int cl = n0w + ni * 8 + (lane & 3) * 2;
            const int j  = cl >> 5;
            const int cc = cl & 31;
#pragma unroll
            for (int rr = 0; rr < 2; ++rr) {
                const int r = m0w + mi * 16 + (lane >> 2) + rr * 8;
                float v0 = fmaxf(acc[mi][ni][2 * rr],     0.f);
                float v1 = fmaxf(acc[mi][ni][2 * rr + 1], 0.f);
                *(uint32_t*)(smem + j * PH_SZ + sw(r * 64 + cc * 2)) = hpack(v0, v1);
            }
        }

    float acc2[NT3][4];
#pragma unroll
    for (int ni = 0; ni < NT3; ++ni)
#pragma unroll
        for (int v = 0; v < 4; ++v) acc2[ni][v] = 0.f;

    __syncthreads();   // P visible; W3 resident since prologue

#pragma unroll
    for (int jg = 0; jg < 4; ++jg) {
#pragma unroll
        for (int ks2 = 0; ks2 < 2; ++ks2) {
            uint32_t ph4[4];
            uint32_t aoff = jg * PH_SZ +
                            sw((wid * 16 + (lane & 15)) * 64 +
                               ks2 * 32 + (lane >> 4) * 16);
            ldsm_x4(ph4, s0 + aoff);
            uint32_t w3h[NT3][2], w3l[NT3][2];
#pragma unroll
            for (int np2 = 0; np2 < NT3 / 2; ++np2) {
                uint32_t rowoff = sw((np2 * 16 + (lane >> 4) * 8 + (lane & 7)) * 64 +
                                     ks2 * 32 + ((lane >> 3) & 1) * 16);
                ldsm_x4(&w3h[2 * np2][0], w3off + jg * (N3 * 64) + rowoff);
                ldsm_x4(&w3l[2 * np2][0], w3off + (4 + jg) * (N3 * 64) + rowoff);
            }
#pragma unroll
            for (int ni = 0; ni < NT3; ++ni) MMA16816(acc2[ni], ph4, w3h[ni]);
#pragma unroll
            for (int ni = 0; ni < NT3; ++ni) MMA16816(acc2[ni], ph4, w3l[ni]);
        }
    }

    float* op = blockIdx.y ? out1 : out0;
    const int r0 = row0 + wid * 16 + (lane >> 2);
#pragma unroll
    for (int ni = 0; ni < NT3; ++ni) {
        const int c = ni * 8 + (lane & 3) * 2;
        *(float2*)(op + (size_t)r0 * N3 + c) =
            make_float2(acc2[ni][0], acc2[ni][1]);
        *(float2*)(op + (size_t)(r0 + 8) * N3 + c) =
            make_float2(acc2[ni][2], acc2[ni][3]);
    }
}

// ===========================================================================
// Edge finalize: one warp per edge. Sums the two layer-3 partials.
// ===========================================================================
__global__ void edge_finalize(const float* __restrict__ ppr_scores,
                              const int* __restrict__ ppr_idx,
                              float* __restrict__ out) {
    int gtid = blockIdx.x * blockDim.x + threadIdx.x;
    int edge = gtid >> 5;
    int lane = gtid & 31;
    if (edge >= E_EDGES) return;

    const float* x0 = g_xnk0 + (size_t)edge * 96;
    const float* x1 = g_xnk1 + (size_t)edge * 96;
    float qv = g_q0[(size_t)edge * 32 + lane] + g_q1[(size_t)edge * 32 + lane];
    float kv = x0[64 + lane] + x1[64 + lane];
    float p  = qv * kv;
#pragma unroll
    for (int off = 16; off > 0; off >>= 1)
        p += __shfl_xor_sync(0xffffffffu, p, off);

    float s = ppr_scores[edge] / (1.f + expf(-p));
    int g = ppr_idx[edge];
    float v0 = (x0[lane]      + x1[lane])      * s;
    float v1 = (x0[32 + lane] + x1[32 + lane]) * s;
    atomicAdd(&out[(size_t)g * 64 + lane],      v0);
    atomicAdd(&out[(size_t)g * 64 + 32 + lane], v1);
}

// ===========================================================================
// Launch sequence (graph-capturable)
// ===========================================================================
extern "C" void kernel_launch(void* const* d_in, const int* in_sizes, int n_in,
                              void* d_out, int out_size) {
    const float* source_attr   = (const float*)d_in[0];
    const float* neighbor_attr = (const float*)d_in[1];
    const float* ppr_scores    = (const float*)d_in[2];
    const int*   ppr_idx       = (const int*)  d_in[3];
    const float* W0  = (const float*)d_in[5];
    const float* W1  = (const float*)d_in[6];
    const float* W2  = (const float*)d_in[7];
    const float* Wqk = (const float*)d_in[8];
    const float* Wk  = (const float*)d_in[9];
    float* out = (float*)d_out;

    __half *h1, *w0t, *w1h, *w1l, *w2qh, *w2ql, *wch, *wcl;
    float *q0, *q1, *x0, *x1;
    cudaGetSymbolAddress((void**)&h1, g_H1);
    cudaGetSymbolAddress((void**)&q0, g_q0);
    cudaGetSymbolAddress((void**)&q1, g_q1);
    cudaGetSymbolAddress((void**)&x0, g_xnk0);
    cudaGetSymbolAddress((void**)&x1, g_xnk1);
    cudaGetSymbolAddress((void**)&w0t, g_W0t);
    cudaGetSymbolAddress((void**)&w1h, g_W1t_hi);
    cudaGetSymbolAddress((void**)&w1l, g_W1t_lo);
    cudaGetSymbolAddress((void**)&w2qh, g_W2qt_hi);
    cudaGetSymbolAddress((void**)&w2ql, g_W2qt_lo);
    cudaGetSymbolAddress((void**)&wch, g_Wct_hi);
    cudaGetSymbolAddress((void**)&wcl, g_Wct_lo);

    // dynamic smem:
    //  L1:          2*24KB              = 49152
    //  L2q (N3=32): 2*24KB + 32*512 B   = 65536
    //  L2x (N3=96): 2*24KB + 96*512 B   = 98304
    constexpr int SML1  = 2 * 24576;
    constexpr int SML2Q = 2 * 24576 + 32 * 512;
    constexpr int SML2X = 2 * 24576 + 96 * 512;
    cudaFuncSetAttribute((const void*)gemm_l1,
                         cudaFuncAttributeMaxDynamicSharedMemorySize, SML1);
    cudaFuncSetAttribute((const void*)gemm_l2<32>,
                         cudaFuncAttributeMaxDynamicSharedMemorySize, SML2Q);
    cudaFuncSetAttribute((const void*)gemm_l2<96>,
                         cudaFuncAttributeMaxDynamicSharedMemorySize, SML2X);

    const int MB = E_EDGES / 128;  // 3125 row tiles

    prep_fold<<<1, 256>>>(W2, Wqk, Wk);
    prep_transpose_split<<<256, 256>>>(W0, W1);
    cudaMemsetAsync(d_out, 0, (size_t)out_size * sizeof(float));

    // ---- source branch: L1, then L2+L3 fused -> q partials ----
    gemm_l1<<<dim3(MB, 2), 256, SML1>>>(source_attr, w0t, h1);
    gemm_l2<32><<<dim3(MB, 2), 256, SML2Q>>>(h1, w1h, w1l, w2qh, w2ql, q0, q1);

    // ---- neighbor branch: L1, then L2+L3 fused -> [xn|k] partials ----
    gemm_l1<<<dim3(MB, 2), 256, SML1>>>(neighbor_attr, w0t, h1);
    gemm_l2<96><<<dim3(MB, 2), 256, SML2X>>>(h1, w1h, w1l, wch, wcl, x0, x1);

    // ---- attention + segment scatter ----
    edge_finalize<<<(E_EDGES * 32 + 255) / 256, 256>>>(ppr_scores, ppr_idx, out);
}

// round 17
// speedup vs baseline: 1.4629x; 1.0002x over previous
#include <cuda_runtime.h>
#include <cuda_fp16.h>
#include <math.h>
#include <stdint.h>

#define E_EDGES 400000
#define NGROUPS 25000

// ===========================================================================
// PTX helpers (sm_80-class only — toolchain targets plain sm_103, no tcgen05)
// ===========================================================================
__device__ __forceinline__ uint32_t smem_u32(const void* p) {
    uint32_t a;
    asm("{ .reg .u64 t; cvta.to.shared.u64 t, %1; cvt.u32.u64 %0, t; }"
        : "=r"(a) : "l"(p));
    return a;
}

#define CP_ASYNC16(sm, gm) \
    asm volatile("cp.async.cg.shared.global [%0], [%1], 16;" \
        :: "r"(sm), "l"(gm) : "memory")
#define CP_COMMIT() asm volatile("cp.async.commit_group;" ::: "memory")
#define CP_WAIT(n)  asm volatile("cp.async.wait_group %0;" :: "n"(n) : "memory")

__device__ __forceinline__ void ldsm_x4(uint32_t* d, uint32_t addr) {
    asm volatile("ldmatrix.sync.aligned.m8n8.x4.shared.b16 {%0,%1,%2,%3}, [%4];"
        : "=r"(d[0]), "=r"(d[1]), "=r"(d[2]), "=r"(d[3]) : "r"(addr));
}

// fp16 in, fp32 accumulate
#define MMA16816(d, a, b) \
    asm volatile("mma.sync.aligned.m16n8k16.row.col.f32.f16.f16.f32 " \
        "{%0,%1,%2,%3}, {%4,%5,%6,%7}, {%8,%9}, {%0,%1,%2,%3};" \
        : "+f"((d)[0]), "+f"((d)[1]), "+f"((d)[2]), "+f"((d)[3]) \
        : "r"((a)[0]), "r"((a)[1]), "r"((a)[2]), "r"((a)[3]), \
          "r"((b)[0]), "r"((b)[1]))

// SW64 swizzle for 64-byte rows (BK=32 fp16)
__device__ __forceinline__ uint32_t sw(uint32_t off) {
    return off ^ ((off >> 3) & 0x30);
}

// ===========================================================================
// Scratch globals (no cudaMalloc allowed)
// ===========================================================================
__device__ __half g_H1[(size_t)E_EDGES * 256];     // H1, single fp16
// fused layer-3 partial outputs (per y-tile, summed in edge_finalize)
__device__ float g_q0  [(size_t)E_EDGES * 32];
__device__ float g_q1  [(size_t)E_EDGES * 32];
__device__ float g_xnk0[(size_t)E_EDGES * 96];
__device__ float g_xnk1[(size_t)E_EDGES * 96];

__device__ float g_W2q [256 * 32];   // W2 @ Wqk  (fp32, [k][n])
__device__ float g_Wcat[256 * 96];   // [W2 | W2@Wk] (fp32, [k][n])
// Transposed weights, [n][k] layout (K contiguous), fp16
__device__ __half g_W0t   [256 * 256];                  // single (B of L1)
__device__ __half g_W1t_hi[256 * 256], g_W1t_lo[256 * 256];
__device__ __half g_W2qt_hi[32 * 256], g_W2qt_lo[32 * 256];
__device__ __half g_Wct_hi[96 * 256],  g_Wct_lo[96 * 256];

__device__ __forceinline__ void hsplit(float v, __half& h, __half& l) {
    h = __float2half_rn(v);
    l = __float2half_rn(v - __half2float(h));
}

// Packed: (v0,v1) -> hi f16x2 word + lo f16x2 word.
__device__ __forceinline__ void hsplit2x2(float v0, float v1,
                                          uint32_t& hw, uint32_t& lw) {
    asm("cvt.rn.f16x2.f32 %0, %1, %2;" : "=r"(hw) : "f"(v1), "f"(v0));
    __half2 hh = *reinterpret_cast<__half2*>(&hw);
    float2 hf = __half22float2(hh);
    asm("cvt.rn.f16x2.f32 %0, %1, %2;" : "=r"(lw) : "f"(v1 - hf.y), "f"(v0 - hf.x));
}

__device__ __forceinline__ uint32_t hpack(float v0, float v1) {
    uint32_t w;
    asm("cvt.rn.f16x2.f32 %0, %1, %2;" : "=r"(w) : "f"(v1), "f"(v0));
    return w;
}

// ===========================================================================
// prep1: fold head projections: g_W2q = W2@Wqk, g_Wcat = [W2 | W2@Wk]
// ===========================================================================
__global__ void prep_fold(const float* __restrict__ W2,
                          const float* __restrict__ Wqk,
                          const float* __restrict__ Wk) {
    __shared__ float sQ[64 * 32];
    __shared__ float sK[64 * 32];
    int tid = threadIdx.x;
    for (int i = tid; i < 64 * 32; i += 256) { sQ[i] = Wqk[i]; sK[i] = Wk[i]; }
    __syncthreads();
    int r = tid;
    float w2r[64];
#pragma unroll
    for (int j = 0; j < 64; ++j) w2r[j] = W2[r * 64 + j];
#pragma unroll 4
    for (int c = 0; c < 32; ++c) {
        float aq = 0.f, ak = 0.f;
#pragma unroll
        for (int j = 0; j < 64; ++j) {
            aq = fmaf(w2r[j], sQ[j * 32 + c], aq);
            ak = fmaf(w2r[j], sK[j * 32 + c], ak);
        }
        g_W2q[r * 32 + c]       = aq;
        g_Wcat[r * 96 + 64 + c] = ak;
    }
#pragma unroll
    for (int j = 0; j < 64; ++j) g_Wcat[r * 96 + j] = w2r[j];
}

// ===========================================================================
// prep2: transpose to [n][k]; W0 single fp16, others split fp16 hi/lo
// ===========================================================================
__global__ void prep_transpose_split(const float* __restrict__ W0,
                                     const float* __restrict__ W1) {
    int t = blockIdx.x * 256 + threadIdx.x;
    int o = t >> 8, i = t & 255;
    __half h, l;
    g_W0t[t] = __float2half_rn(W0[i * 256 + o]);
    hsplit(W1[i * 256 + o], h, l);  g_W1t_hi[t] = h;  g_W1t_lo[t] = l;
    if (o < 32) { hsplit(g_W2q[i * 32 + o], h, l);  g_W2qt_hi[t] = h; g_W2qt_lo[t] = l; }
    if (o < 96) { hsplit(g_Wcat[i * 96 + o], h, l); g_Wct_hi[t] = h;  g_Wct_lo[t] = l; }
}

// ===========================================================================
// L1 GEMM (fp16x2, A split / B single):
//   H1 = relu( X @ W0 ),  computed as Xh*W0h + Xl*W0h  (W0h = fp16(W0))
// A = X fp32 in gmem: LDG prefetch + in-register split + STS (FP32A path).
// BM=128, BN=128, BK=32, 8 chunks, 2-stage. Stage = Ah(8K)+Al(8K)+B(8K)=24KB.
// Epilogue: relu + single fp16 store (width 256).
// ===========================================================================
__global__ void __launch_bounds__(256, 2)
gemm_l1(const float* __restrict__ Afp, const __half* __restrict__ Bw,
        __half* __restrict__ outH) {
    constexpr int BN    = 128;
    constexpr int NB    = 8;
    constexpr int A_CH  = 128 * 64;
    constexpr int B_CH  = BN * 64;
    constexpr int STAGE = 2 * A_CH + B_CH;   // 24 KB

    extern __shared__ char smem[];
    const uint32_t s0 = smem_u32(smem);

    const int tid  = threadIdx.x;
    const int lane = tid & 31;
    const int wid  = tid >> 5;
    const int m0w  = (wid & 3) * 32;
    const int n0w  = (wid >> 2) * 64;
    const int row0 = blockIdx.x * 128;
    const int col0 = blockIdx.y * BN;

    float acc[2][NB][4];
#pragma unroll
    for (int mi = 0; mi < 2; ++mi)
#pragma unroll
        for (int ni = 0; ni < NB; ++ni)
#pragma unroll
            for (int v = 0; v < 4; ++v) acc[mi][ni][v] = 0.f;

    float4 pf[4];

    auto loadB = [&](int c, int buf) {
        const int kk = c << 5;
#pragma unroll
        for (int i = tid; i < BN * 4; i += 256) {
            int n = i >> 2, g = i & 3;
            const __half* src = Bw + (size_t)(col0 + n) * 256 + kk + g * 8;
            CP_ASYNC16(s0 + buf * STAGE + 2 * A_CH + sw(n * 64 + g * 16), src);
        }
    };
    auto ldA_f32 = [&](int c) {
        const int kk = c << 5;
#pragma unroll
        for (int j = 0; j < 4; ++j) {
            int f4 = tid + 256 * j;
            int r = f4 >> 3, c4 = f4 & 7;
            pf[j] = *(const float4*)(Afp + (size_t)(row0 + r) * 256 + kk + c4 * 4);
        }
    };
    auto stA_f32 = [&](int buf) {
#pragma unroll
        for (int j = 0; j < 4; ++j) {
            int f4 = tid + 256 * j;
            int r = f4 >> 3, c4 = f4 & 7;
            uint2 hw, lw;
            hsplit2x2(pf[j].x, pf[j].y, hw.x, lw.x);
            hsplit2x2(pf[j].z, pf[j].w, hw.y, lw.y);
            uint32_t off = buf * STAGE + sw(r * 64 + c4 * 8);
            *(uint2*)(smem + off)        = hw;
            *(uint2*)(smem + off + A_CH) = lw;
        }
    };

    ldA_f32(0); stA_f32(0);
    loadB(0, 0); CP_COMMIT();

#pragma unroll 1
    for (int c = 0; c < 8; ++c) {
        if (c < 7) {
            ldA_f32(c + 1);
            loadB(c + 1, (c + 1) & 1);
            CP_COMMIT();
            CP_WAIT(1);
        } else {
            CP_WAIT(0);
        }
        __syncthreads();

        const uint32_t st = s0 + (c & 1) * STAGE;
        const uint32_t db = st + 2 * A_CH;
#pragma unroll
        for (int ks = 0; ks < 2; ++ks) {
            uint32_t ah[2][4], al[2][4];
#pragma unroll
            for (int mi = 0; mi < 2; ++mi) {
                uint32_t aoff = sw((m0w + mi * 16 + (lane & 15)) * 64 +
                                   ks * 32 + (lane >> 4) * 16);
                ldsm_x4(ah[mi], st + aoff);
                ldsm_x4(al[mi], st + A_CH + aoff);
            }
            uint32_t bh[NB][2];
#pragma unroll
            for (int np = 0; np < NB / 2; ++np) {
                uint32_t boff = sw((n0w + np * 16 + (lane >> 4) * 8 + (lane & 7)) * 64 +
                                   ks * 32 + ((lane >> 3) & 1) * 16);
                ldsm_x4(&bh[2 * np][0], db + boff);
            }
#pragma unroll
            for (int mi = 0; mi < 2; ++mi)
#pragma unroll
                for (int ni = 0; ni < NB; ++ni)
                    MMA16816(acc[mi][ni], ah[mi], bh[ni]);
#pragma unroll
            for (int mi = 0; mi < 2; ++mi)
#pragma unroll
                for (int ni = 0; ni < NB; ++ni)
                    MMA16816(acc[mi][ni], al[mi], bh[ni]);
        }
        if (c < 7) stA_f32((c + 1) & 1);
        __syncthreads();
    }

    // epilogue: relu + single fp16
    const int rbase = row0 + m0w + (lane >> 2);
#pragma unroll
    for (int mi = 0; mi < 2; ++mi) {
        const int r0 = rbase + mi * 16;
#pragma unroll
        for (int ni = 0; ni < NB; ++ni) {
            const int c = col0 + n0w + ni * 8 + (lane & 3) * 2;
#pragma unroll
            for (int h = 0; h < 2; ++h) {
                float v0 = fmaxf(acc[mi][ni][2 * h],     0.f);
                float v1 = fmaxf(acc[mi][ni][2 * h + 1], 0.f);
                *(uint32_t*)(outH + (size_t)(r0 + h * 8) * 256 + c) = hpack(v0, v1);
            }
        }
    }
}

// ===========================================================================
// L2 GEMM + fused L3 (fp16x2, A single / B split):
//   H2 = relu( H1 @ W1 ) = relu( A*W1h + A*W1l ),  A = H1 fp16
//   G  = relu(H2)_fp16 @ (W3h + W3l)  -> fp32 partial per y-tile
// Stage = A(8K)+Bh(8K)+Bl(8K)=24KB, 2 stages. W3 prefetched in prologue.
// ===========================================================================
template <int N3>
__global__ void __launch_bounds__(256, 2)
gemm_l2(const __half* __restrict__ Ain,
        const __half* __restrict__ Bh_, const __half* __restrict__ Bl_,
        const __half* __restrict__ W3h, const __half* __restrict__ W3l,
        float* __restrict__ out0, float* __restrict__ out1) {
    constexpr int BN    = 128;
    constexpr int NB    = 8;
    constexpr int A_CH  = 128 * 64;
    constexpr int B_CH  = BN * 64;
    constexpr int STAGE = A_CH + 2 * B_CH;   // 24 KB

    extern __shared__ char smem[];
    const uint32_t s0 = smem_u32(smem);
    const uint32_t w3off = s0 + 2 * STAGE;

    const int tid  = threadIdx.x;
    const int lane = tid & 31;
    const int wid  = tid >> 5;
    const int m0w  = (wid & 3) * 32;
    const int n0w  = (wid >> 2) * 64;
    const int row0 = blockIdx.x * 128;
    const int col0 = blockIdx.y * BN;

    float acc[2][NB][4];
#pragma unroll
    for (int mi = 0; mi < 2; ++mi)
#pragma unroll
        for (int ni = 0; ni < NB; ++ni)
#pragma unroll
            for (int v = 0; v < 4; ++v) acc[mi][ni][v] = 0.f;

    auto loadA = [&](int c, int buf) {
        const int kk = c << 5;
#pragma unroll
        for (int i = tid; i < 512; i += 256) {
            int r = i >> 2, g = i & 3;
            const __half* src = Ain + (size_t)(row0 + r) * 256 + kk + g * 8;
            CP_ASYNC16(s0 + buf * STAGE + sw(r * 64 + g * 16), src);
        }
    };
    auto loadB = [&](int c, int buf) {
        const int kk = c << 5;
#pragma unroll
        for (int i = tid; i < 2 * BN * 4; i += 256) {
            int sp = i / (BN * 4), idx = i % (BN * 4), n = idx >> 2, g = idx & 3;
            const __half* src =
                (sp ? Bl_ : Bh_) + (size_t)(col0 + n) * 256 + kk + g * 8;
            CP_ASYNC16(s0 + buf * STAGE + A_CH + sp * B_CH + sw(n * 64 + g * 16), src);
        }
    };

    // ---- prologue: W3 prefetch (resident through mainloop), then chunk 0 ----
#pragma unroll
    for (int i = tid; i < 2 * 4 * N3 * 4; i += 256) {
        int sp = i / (4 * N3 * 4), r1 = i % (4 * N3 * 4);
        int kc = r1 / (N3 * 4),   r2 = r1 % (N3 * 4);
        int n  = r2 >> 2,         g  = r2 & 3;
        const __half* src =
            (sp ? W3l : W3h) + (size_t)n * 256 + col0 + kc * 32 + g * 8;
        CP_ASYNC16(w3off + (sp * 4 + kc) * (N3 * 64) + sw(n * 64 + g * 16), src);
    }
    CP_COMMIT();
    loadA(0, 0); loadB(0, 0); CP_COMMIT();

#pragma unroll 1
    for (int c = 0; c < 8; ++c) {
        if (c < 7) {
            loadA(c + 1, (c + 1) & 1);
            loadB(c + 1, (c + 1) & 1);
            CP_COMMIT();
            CP_WAIT(1);
        } else {
            CP_WAIT(0);
        }
        __syncthreads();

        const uint32_t st = s0 + (c & 1) * STAGE;
        const uint32_t db = st + A_CH;
#pragma unroll
        for (int ks = 0; ks < 2; ++ks) {
            uint32_t ah[2][4];
#pragma unroll
            for (int mi = 0; mi < 2; ++mi) {
                uint32_t aoff = sw((m0w + mi * 16 + (lane & 15)) * 64 +
                                   ks * 32 + (lane >> 4) * 16);
                ldsm_x4(ah[mi], st + aoff);
            }
            uint32_t bh[NB][2], bl[NB][2];
#pragma unroll
            for (int np = 0; np < NB / 2; ++np) {
                uint32_t boff = sw((n0w + np * 16 + (lane >> 4) * 8 + (lane & 7)) * 64 +
                                   ks * 32 + ((lane >> 3) & 1) * 16);
                ldsm_x4(&bh[2 * np][0], db + boff);
                ldsm_x4(&bl[2 * np][0], db + B_CH + boff);
            }
#pragma unroll
            for (int mi = 0; mi < 2; ++mi)
#pragma unroll
                for (int ni = 0; ni < NB; ++ni)
                    MMA16816(acc[mi][ni], ah[mi], bh[ni]);
#pragma unroll
            for (int mi = 0; mi < 2; ++mi)
#pragma unroll
                for (int ni = 0; ni < NB; ++ni)
                    MMA16816(acc[mi][ni], ah[mi], bl[ni]);
        }
        __syncthreads();
    }

    // ---- fused layer-3 ----
    constexpr int NT3   = N3 / 8;
    constexpr int PH_SZ = 128 * 64;      // one K=32 chunk of P, fp16 single
    // P region overlays stage buffers (4 chunks x 8KB = 32KB <= 48KB)

    // stage P tile (this warp's 64 cols, rows it owns), relu + single fp16
#pragma unroll
    for (int mi = 0; mi < 2; ++mi)
#pragma unroll
        for (int ni = 0; ni < NB; ++ni) {
            const int cl = n0w + ni * 8 + (lane & 3) * 2;
            const int j  = cl >> 5;
            const int cc = cl & 31;
#pragma unroll
            for (int rr = 0; rr < 2; ++rr) {
                const int r = m0w + mi * 16 + (lane >> 2) + rr * 8;
                float v0 = fmaxf(acc[mi][ni][2 * rr],     0.f);
                float v1 = fmaxf(acc[mi][ni][2 * rr + 1], 0.f);
                *(uint32_t*)(smem + j * PH_SZ + sw(r * 64 + cc * 2)) = hpack(v0, v1);
            }
        }

    float acc2[NT3][4];
#pragma unroll
    for (int ni = 0; ni < NT3; ++ni)
#pragma unroll
        for (int v = 0; v < 4; ++v) acc2[ni][v] = 0.f;

    __syncthreads();   // P visible; W3 resident since prologue

#pragma unroll
    for (int jg = 0; jg < 4; ++jg) {
#pragma unroll
        for (int ks2 = 0; ks2 < 2; ++ks2) {
            uint32_t ph4[4];
            uint32_t aoff = jg * PH_SZ +
                            sw((wid * 16 + (lane & 15)) * 64 +
                               ks2 * 32 + (lane >> 4) * 16);
            ldsm_x4(ph4, s0 + aoff);
            uint32_t w3h[NT3][2], w3l[NT3][2];
#pragma unroll
            for (int np2 = 0; np2 < NT3 / 2; ++np2) {
                uint32_t rowoff = sw((np2 * 16 + (lane >> 4) * 8 + (lane & 7)) * 64 +
                                     ks2 * 32 + ((lane >> 3) & 1) * 16);
                ldsm_x4(&w3h[2 * np2][0], w3off + jg * (N3 * 64) + rowoff);
                ldsm_x4(&w3l[2 * np2][0], w3off + (4 + jg) * (N3 * 64) + rowoff);
            }
#pragma unroll
            for (int ni = 0; ni < NT3; ++ni) MMA16816(acc2[ni], ph4, w3h[ni]);
#pragma unroll
            for (int ni = 0; ni < NT3; ++ni) MMA16816(acc2[ni], ph4, w3l[ni]);
        }
    }

    float* op = blockIdx.y ? out1 : out0;
    const int r0 = row0 + wid * 16 + (lane >> 2);
#pragma unroll
    for (int ni = 0; ni < NT3; ++ni) {
        const int c = ni * 8 + (lane & 3) * 2;
        *(float2*)(op + (size_t)r0 * N3 + c) =
            make_float2(acc2[ni][0], acc2[ni][1]);
        *(float2*)(op + (size_t)(r0 + 8) * N3 + c) =
            make_float2(acc2[ni][2], acc2[ni][3]);
    }
}

// ===========================================================================
// Edge finalize: one warp per edge. Sums the two layer-3 partials.
// ===========================================================================
__global__ void edge_finalize(const float* __restrict__ ppr_scores,
                              const int* __restrict__ ppr_idx,
                              float* __restrict__ out) {
    int gtid = blockIdx.x * blockDim.x + threadIdx.x;
    int edge = gtid >> 5;
    int lane = gtid & 31;
    if (edge >= E_EDGES) return;

    const float* x0 = g_xnk0 + (size_t)edge * 96;
    const float* x1 = g_xnk1 + (size_t)edge * 96;
    float qv = g_q0[(size_t)edge * 32 + lane] + g_q1[(size_t)edge * 32 + lane];
    float kv = x0[64 + lane] + x1[64 + lane];
    float p  = qv * kv;
#pragma unroll
    for (int off = 16; off > 0; off >>= 1)
        p += __shfl_xor_sync(0xffffffffu, p, off);

    float s = ppr_scores[edge] / (1.f + expf(-p));
    int g = ppr_idx[edge];
    float v0 = (x0[lane]      + x1[lane])      * s;
    float v1 = (x0[32 + lane] + x1[32 + lane]) * s;
    atomicAdd(&out[(size_t)g * 64 + lane],      v0);
    atomicAdd(&out[(size_t)g * 64 + 32 + lane], v1);
}

// ===========================================================================
// Launch sequence (graph-capturable)
// ===========================================================================
extern "C" void kernel_launch(void* const* d_in, const int* in_sizes, int n_in,
                              void* d_out, int out_size) {
    const float* source_attr   = (const float*)d_in[0];
    const float* neighbor_attr = (const float*)d_in[1];
    const float* ppr_scores    = (const float*)d_in[2];
    const int*   ppr_idx       = (const int*)  d_in[3];
    const float* W0  = (const float*)d_in[5];
    const float* W1  = (const float*)d_in[6];
    const float* W2  = (const float*)d_in[7];
    const float* Wqk = (const float*)d_in[8];
    const float* Wk  = (const float*)d_in[9];
    float* out = (float*)d_out;

    __half *h1, *w0t, *w1h, *w1l, *w2qh, *w2ql, *wch, *wcl;
    float *q0, *q1, *x0, *x1;
    cudaGetSymbolAddress((void**)&h1, g_H1);
    cudaGetSymbolAddress((void**)&q0, g_q0);
    cudaGetSymbolAddress((void**)&q1, g_q1);
    cudaGetSymbolAddress((void**)&x0, g_xnk0);
    cudaGetSymbolAddress((void**)&x1, g_xnk1);
    cudaGetSymbolAddress((void**)&w0t, g_W0t);
    cudaGetSymbolAddress((void**)&w1h, g_W1t_hi);
    cudaGetSymbolAddress((void**)&w1l, g_W1t_lo);
    cudaGetSymbolAddress((void**)&w2qh, g_W2qt_hi);
    cudaGetSymbolAddress((void**)&w2ql, g_W2qt_lo);
    cudaGetSymbolAddress((void**)&wch, g_Wct_hi);
    cudaGetSymbolAddress((void**)&wcl, g_Wct_lo);

    // dynamic smem:
    //  L1:          2*24KB              = 49152
    //  L2q (N3=32): 2*24KB + 32*512 B   = 65536
    //  L2x (N3=96): 2*24KB + 96*512 B   = 98304
    constexpr int SML1  = 2 * 24576;
    constexpr int SML2Q = 2 * 24576 + 32 * 512;
    constexpr int SML2X = 2 * 24576 + 96 * 512;
    cudaFuncSetAttribute((const void*)gemm_l1,
                         cudaFuncAttributeMaxDynamicSharedMemorySize, SML1);
    cudaFuncSetAttribute((const void*)gemm_l2<32>,
                         cudaFuncAttributeMaxDynamicSharedMemorySize, SML2Q);
    cudaFuncSetAttribute((const void*)gemm_l2<96>,
                         cudaFuncAttributeMaxDynamicSharedMemorySize, SML2X);

    const int MB = E_EDGES / 128;  // 3125 row tiles

    prep_fold<<<1, 256>>>(W2, Wqk, Wk);
    prep_transpose_split<<<256, 256>>>(W0, W1);
    cudaMemsetAsync(d_out, 0, (size_t)out_size * sizeof(float));

    // ---- source branch: L1, then L2+L3 fused -> q partials ----
    gemm_l1<<<dim3(MB, 2), 256, SML1>>>(source_attr, w0t, h1);
    gemm_l2<32><<<dim3(MB, 2), 256, SML2Q>>>(h1, w1h, w1l, w2qh, w2ql, q0, q1);

    // ---- neighbor branch: L1, then L2+L3 fused -> [xn|k] partials ----
    gemm_l1<<<dim3(MB, 2), 256, SML1>>>(neighbor_attr, w0t, h1);
    gemm_l2<96><<<dim3(MB, 2), 256, SML2X>>>(h1, w1h, w1l, wch, wcl, x0, x1);

    // ---- attention + segment scatter ----
    edge_finalize<<<(E_EDGES * 32 + 255) / 256, 256>>>(ppr_scores, ppr_idx, out);
}